// round 12
// baseline (speedup 1.0000x reference)
#include <cuda_runtime.h>
#include <cuda_fp16.h>
#include <mma.h>
#include <math.h>
#include <stddef.h>
#include <stdint.h>

using namespace nvcuda;

// ---------------- problem constants ----------------
#define NS   4096
#define NG   20000
#define NGP  20096
#define NE   131072
#define DIN  256
#define H    4
#define C1   64
#define C3   128
#define HC1  256
#define HC3  512

// ---------------- device scratch ----------------
__device__ __align__(128) float g_xl_sg[NS * HC1];
__device__ __align__(128) float g_xr_sg[NGP * HC1];
__device__ __align__(128) float g_xl_gs[NGP * HC1];
__device__ __align__(128) float g_xr_gs[NS * HC1];
__device__ __align__(128) float g_sl1[NS * C1];
__device__ __align__(128) float g_xl3[NGP * HC3];
__device__ __align__(128) float g_xr3[NS * HC3];
__device__ __align__(128) float g_sl3[NS * C3];
__device__ __align__(128) float g_b5p[128];

__device__ __align__(128) __half g_hxs[NS * DIN];
__device__ __align__(128) __half g_hxg[NG * DIN];
__device__ __align__(128) __half g_hWl1sg[DIN * HC1];
__device__ __align__(128) __half g_hWr1sg[DIN * HC1];
__device__ __align__(128) __half g_hWl1gs[DIN * HC1];
__device__ __align__(128) __half g_hWr1gs[DIN * HC1];
__device__ __align__(128) __half g_hw5[DIN * 128];
__device__ __align__(128) __half g_hWl3[DIN * HC3];
__device__ __align__(128) __half g_hWr3[DIN * HC3];
__device__ __align__(128) __half g_hsl3W[DIN * C3];
__device__ __align__(128) __half g_x1h_gene[NG * HC1];
__device__ __align__(128) __half g_x1h_sample[NS * HC1];

__device__ int g_deg_sg[NG];
__device__ int g_deg_gs[NS];
__device__ int g_off_sg[NG + 1];
__device__ int g_cur_sg[NG];
__device__ int g_srcs_sg[NE];
__device__ int g_off_gs[NS + 1];
__device__ int g_cur_gs[NS];
__device__ int g_srcs_gs[NE];

// ---------------- helpers ----------------
__device__ __forceinline__ uint32_t smem_u32(const void* p) {
    uint32_t a;
    asm("{ .reg .u64 t; cvta.to.shared.u64 t, %1; cvt.u32.u64 %0, t; }" : "=r"(a) : "l"(p));
    return a;
}
#define CP_ASYNC16(dst, src) \
    asm volatile("cp.async.ca.shared.global [%0], [%1], 16;" :: "r"(dst), "l"(src))
#define CP_COMMIT() asm volatile("cp.async.commit_group;")
#define CP_WAIT(n)  asm volatile("cp.async.wait_group %0;" :: "n"(n))

// ---------------- fp32 -> fp16 conversion ----------------
__global__ void cvt_all(const float* __restrict__ xs, const float* __restrict__ xg,
                        const float* __restrict__ Wl1sg, const float* __restrict__ Wr1sg,
                        const float* __restrict__ Wl1gs, const float* __restrict__ Wr1gs,
                        const float* __restrict__ w5, const float* __restrict__ b5,
                        const float* __restrict__ Wl3, const float* __restrict__ Wr3,
                        const float* __restrict__ sl3W,
                        __half* __restrict__ hxs, __half* __restrict__ hxg,
                        __half* __restrict__ hWl1sg, __half* __restrict__ hWr1sg,
                        __half* __restrict__ hWl1gs, __half* __restrict__ hWr1gs,
                        __half* __restrict__ hw5, float* __restrict__ b5p,
                        __half* __restrict__ hWl3, __half* __restrict__ hWr3,
                        __half* __restrict__ hsl3W) {
    int i = blockIdx.x * blockDim.x + threadIdx.x;
    if (i < NS * DIN) hxs[i] = __float2half(xs[i]);
    if (i < NG * DIN) hxg[i] = __float2half(xg[i]);
    if (i < DIN * HC1) {
        hWl1sg[i] = __float2half(Wl1sg[i]);
        hWr1sg[i] = __float2half(Wr1sg[i]);
        hWl1gs[i] = __float2half(Wl1gs[i]);
        hWr1gs[i] = __float2half(Wr1gs[i]);
    }
    if (i < DIN * 128) {
        int k = i >> 7, c = i & 127;
        hw5[i] = (c < C1) ? __float2half(w5[k * C1 + c]) : __half(0.f);
        hsl3W[i] = __float2half(sl3W[i]);
    }
    if (i < 128) b5p[i] = (i < C1) ? b5[i] : 0.f;
    if (i < DIN * HC3) {
        hWl3[i] = __float2half(Wl3[i]);
        hWr3[i] = __float2half(Wr3[i]);
    }
}

// ---------------- batched fp16 WMMA GEMM (fp32 accum) ----------------
struct GemmSeg {
    const __half* A; const __half* B; const float* bias; float* C;
    int ldB; int M; int Nout; int nx; int blk0;
};
struct GemmBatch { GemmSeg seg[6]; int nseg; };

#define GEMM_THREADS 256
#define A_PITCH_H 72
#define B_PITCH_H 136
#define A_BUF_B   18432
#define B_BUF_B   17408
#define B_BASE_B  36864
#define GEMM_SMEM 71680

__global__ void __launch_bounds__(GEMM_THREADS) gemm_batch(GemmBatch P) {
    extern __shared__ char smc[];
    const int tid = threadIdx.x;
    const int wid = tid >> 5;
    const int warp_m = wid >> 1;
    const int warp_n = wid & 1;

    GemmSeg g = P.seg[0];
    #pragma unroll
    for (int i = 1; i < 6; i++)
        if (i < P.nseg && (int)blockIdx.x >= P.seg[i].blk0) g = P.seg[i];
    int lb = blockIdx.x - g.blk0;
    const int m0 = (lb / g.nx) * 128;
    const int col0 = (lb % g.nx) * 128;

    wmma::fragment<wmma::accumulator, 16, 16, 16, float> cfr[2][4];
    #pragma unroll
    for (int i = 0; i < 2; i++)
        #pragma unroll
        for (int t = 0; t < 4; t++) wmma::fill_fragment(cfr[i][t], 0.f);

    auto loadA = [&](int s, int b) {
        const __half* Ab = g.A + (size_t)m0 * 256 + s * 64;
        char* dst = smc + b * A_BUF_B;
        #pragma unroll
        for (int i = 0; i < 4; i++) {
            int ch = tid + i * 256;
            int r = ch >> 3, c8 = ch & 7;
            char* dp = dst + r * 144 + c8 * 16;
            if (m0 + r < g.M) {
                CP_ASYNC16(smem_u32(dp), Ab + (size_t)r * 256 + c8 * 8);
            } else {
                *(uint4*)dp = make_uint4(0, 0, 0, 0);
            }
        }
    };
    auto loadB = [&](int s, int b) {
        const __half* Bb = g.B + (size_t)(s * 64) * g.ldB + col0;
        char* dst = smc + B_BASE_B + b * B_BUF_B;
        #pragma unroll
        for (int i = 0; i < 4; i++) {
            int ch = tid + i * 256;
            int r = ch >> 4, c8 = ch & 15;
            CP_ASYNC16(smem_u32(dst + r * 272 + c8 * 16), Bb + (size_t)r * g.ldB + c8 * 8);
        }
    };

    loadA(0, 0); loadB(0, 0);
    CP_COMMIT();

    #pragma unroll 1
    for (int s = 0; s < 4; s++) {
        int b = s & 1;
        if (s < 3) { loadA(s + 1, b ^ 1); loadB(s + 1, b ^ 1); CP_COMMIT(); }
        if (s < 3) { CP_WAIT(1); } else { CP_WAIT(0); }
        __syncthreads();

        const __half* As = (const __half*)(smc + b * A_BUF_B) + warp_m * 32 * A_PITCH_H;
        const __half* Bs = (const __half*)(smc + B_BASE_B + b * B_BUF_B);
        #pragma unroll
        for (int kk = 0; kk < 4; kk++) {
            wmma::fragment<wmma::matrix_a, 16, 16, 16, __half, wmma::row_major> af[2];
            wmma::load_matrix_sync(af[0], As + kk * 16, A_PITCH_H);
            wmma::load_matrix_sync(af[1], As + 16 * A_PITCH_H + kk * 16, A_PITCH_H);
            #pragma unroll
            for (int t = 0; t < 4; t++) {
                wmma::fragment<wmma::matrix_b, 16, 16, 16, __half, wmma::row_major> bf;
                wmma::load_matrix_sync(bf, Bs + kk * 16 * B_PITCH_H + warp_n * 64 + t * 16, B_PITCH_H);
                wmma::mma_sync(cfr[0][t], af[0], bf, cfr[0][t]);
                wmma::mma_sync(cfr[1][t], af[1], bf, cfr[1][t]);
            }
        }
        __syncthreads();
    }

    float* stg = (float*)smc;
    #pragma unroll
    for (int i = 0; i < 2; i++)
        #pragma unroll
        for (int t = 0; t < 4; t++)
            wmma::store_matrix_sync(stg + (warp_m * 32 + i * 16) * 132 + warp_n * 64 + t * 16,
                                    cfr[i][t], 132, wmma::mem_row_major);
    __syncthreads();

    #pragma unroll
    for (int id = tid; id < 128 * 32; id += 256) {
        int r = id >> 5;
        int c = (id & 31) * 4;
        if (col0 + c < g.Nout) {
            float4 v = *(const float4*)(stg + r * 132 + c);
            float4 bv = *(const float4*)(g.bias + col0 + c);
            v.x += bv.x; v.y += bv.y; v.z += bv.z; v.w += bv.w;
            *(float4*)(g.C + (size_t)(m0 + r) * g.Nout + col0 + c) = v;
        }
    }
}

// ---------------- CSR build ----------------
__global__ void count2_kernel(const int* __restrict__ sg_dst, const int* __restrict__ gs_dst,
                              int* __restrict__ dsg, int* __restrict__ dgs) {
    int e = blockIdx.x * blockDim.x + threadIdx.x;
    if (e < NE) {
        atomicAdd(&dsg[sg_dst[e]], 1);
        atomicAdd(&dgs[gs_dst[e]], 1);
    }
}

// single-pass chunked scan: thread t serially prefixes CH elements, block-scan
// over 1024 per-thread sums, write offsets + cur. grid=2 (sg: CH=20, gs: CH=4).
__global__ void scan2_kernel(const int* __restrict__ dsg, int* __restrict__ off_sg, int* __restrict__ cur_sg,
                             const int* __restrict__ dgs, int* __restrict__ off_gs, int* __restrict__ cur_gs) {
    const int* deg = (blockIdx.x == 0) ? dsg : dgs;
    int* off = (blockIdx.x == 0) ? off_sg : off_gs;
    int* cur = (blockIdx.x == 0) ? cur_sg : cur_gs;
    const int n  = (blockIdx.x == 0) ? NG : NS;
    const int ch = (blockIdx.x == 0) ? 20 : 4;
    __shared__ int wsum[32];
    int tid = threadIdx.x, lane = tid & 31, wid = tid >> 5;
    int base = tid * ch;

    int vals[20];
    int tsum = 0;
    #pragma unroll 20
    for (int j = 0; j < 20; j++) {
        if (j < ch) {
            int i = base + j;
            int v = (i < n) ? deg[i] : 0;
            vals[j] = tsum;       // exclusive within chunk
            tsum += v;
        }
    }
    // block scan of tsum
    int x = tsum;
    #pragma unroll
    for (int o = 1; o < 32; o <<= 1) {
        int t = __shfl_up_sync(0xFFFFFFFFu, x, o);
        if (lane >= o) x += t;
    }
    if (lane == 31) wsum[wid] = x;
    __syncthreads();
    if (wid == 0) {
        int y = wsum[lane];
        #pragma unroll
        for (int o = 1; o < 32; o <<= 1) {
            int t = __shfl_up_sync(0xFFFFFFFFu, y, o);
            if (lane >= o) y += t;
        }
        wsum[lane] = y;
    }
    __syncthreads();
    int pre = (wid > 0) ? wsum[wid - 1] : 0;
    int tbase = pre + x - tsum;     // exclusive prefix of this thread's chunk

    #pragma unroll 20
    for (int j = 0; j < 20; j++) {
        if (j < ch) {
            int i = base + j;
            if (i < n) {
                int e = tbase + vals[j];
                off[i] = e;
                cur[i] = e;
            }
        }
    }
    if (tid == 0) off[n] = wsum[31];
}

__global__ void scatter2_kernel(const int* __restrict__ sg_src, const int* __restrict__ sg_dst,
                                int* __restrict__ cur_sg, int* __restrict__ srcs_sg,
                                const int* __restrict__ gs_src, const int* __restrict__ gs_dst,
                                int* __restrict__ cur_gs, int* __restrict__ srcs_gs) {
    int e = blockIdx.x * blockDim.x + threadIdx.x;
    if (e < NE) {
        int p = atomicAdd(&cur_sg[sg_dst[e]], 1);
        srcs_sg[p] = sg_src[e];
        int q = atomicAdd(&cur_gs[gs_dst[e]], 1);
        srcs_gs[q] = gs_src[e];
    }
}

// ---------------- layer-1 GAT core: warp per dst, 4 heads, half output ----------------
__device__ __forceinline__ void gat1_core(int d, int lane,
                                          const int* __restrict__ off, const int* __restrict__ srcs,
                                          const float* __restrict__ xl, const float* __restrict__ xr,
                                          const float* __restrict__ att, const float* __restrict__ bias,
                                          const float* __restrict__ self, __half* __restrict__ out) {
    float attv[8], xrv[8];
    {
        const float4* pa = (const float4*)(att + lane * 8);
        const float4* pr = (const float4*)(xr + (size_t)d * HC1 + lane * 8);
        float4 a0 = pa[0], a1 = pa[1], r0 = pr[0], r1 = pr[1];
        attv[0]=a0.x; attv[1]=a0.y; attv[2]=a0.z; attv[3]=a0.w;
        attv[4]=a1.x; attv[5]=a1.y; attv[6]=a1.z; attv[7]=a1.w;
        xrv[0]=r0.x; xrv[1]=r0.y; xrv[2]=r0.z; xrv[3]=r0.w;
        xrv[4]=r1.x; xrv[5]=r1.y; xrv[6]=r1.z; xrv[7]=r1.w;
    }
    int b0 = off[d], b1 = off[d + 1];

    float m = -1e30f, den = 0.f, acc[8] = {};
    int s = (b0 < b1) ? srcs[b0] : 0;
    for (int i = b0; i < b1; i++) {
        int s_next = (i + 1 < b1) ? srcs[i + 1] : 0;
        const float4* p = (const float4*)(xl + (size_t)s * HC1 + lane * 8);
        float4 t0 = p[0], t1 = p[1];
        float t[8] = {t0.x, t0.y, t0.z, t0.w, t1.x, t1.y, t1.z, t1.w};
        float pp = 0.f;
        #pragma unroll
        for (int v = 0; v < 8; v++) {
            float g = t[v] + xrv[v];
            g = g > 0.f ? g : 0.2f * g;
            pp = fmaf(g, attv[v], pp);
        }
        pp += __shfl_xor_sync(0xFFFFFFFFu, pp, 1);
        pp += __shfl_xor_sync(0xFFFFFFFFu, pp, 2);
        pp += __shfl_xor_sync(0xFFFFFFFFu, pp, 4);
        float mn = fmaxf(m, pp);
        float sc = __expf(m - mn);
        float a  = __expf(pp - mn);
        den = den * sc + a;
        #pragma unroll
        for (int v = 0; v < 8; v++) acc[v] = fmaf(acc[v], sc, a * t[v]);
        m = mn;
        s = s_next;
    }

    float inv = 1.f / (den + 1e-16f);
    float ov[8];
    #pragma unroll
    for (int v = 0; v < 8; v++) {
        float x = acc[v] * inv + bias[lane * 8 + v];
        if (self) x += self[(size_t)d * C1 + (lane & 7) * 8 + v];
        ov[v] = x > 0.f ? x : (__expf(x) - 1.f);
    }
    __half2 hv[4];
    #pragma unroll
    for (int j = 0; j < 4; j++) hv[j] = __floats2half2_rn(ov[2 * j], ov[2 * j + 1]);
    *(uint4*)(out + (size_t)d * HC1 + lane * 8) = *(uint4*)hv;
}

__global__ void gat1_dual(const int* __restrict__ off_sg, const int* __restrict__ srcs_sg,
                          const float* __restrict__ xl_sg, const float* __restrict__ xr_sg,
                          const float* __restrict__ att_sg, const float* __restrict__ bias_sg,
                          __half* __restrict__ out_sg,
                          const int* __restrict__ off_gs, const int* __restrict__ srcs_gs,
                          const float* __restrict__ xl_gs, const float* __restrict__ xr_gs,
                          const float* __restrict__ att_gs, const float* __restrict__ bias_gs,
                          const float* __restrict__ self_gs, __half* __restrict__ out_gs) {
    int w = (blockIdx.x * blockDim.x + threadIdx.x) >> 5;
    int lane = threadIdx.x & 31;
    if (w < NG) {
        gat1_core(w, lane, off_sg, srcs_sg, xl_sg, xr_sg, att_sg, bias_sg, nullptr, out_sg);
    } else if (w < NG + NS) {
        gat1_core(w - NG, lane, off_gs, srcs_gs, xl_gs, xr_gs, att_gs, bias_gs, self_gs, out_gs);
    }
}

// ---------------- layer-3 GAT: warp per dst, head mean via shfl ----------------
__global__ void gat3_warp(const int* __restrict__ off, const int* __restrict__ srcs,
                          const float* __restrict__ xl, const float* __restrict__ xr,
                          const float* __restrict__ att, const float* __restrict__ bias3,
                          const float* __restrict__ sl3, float* __restrict__ out) {
    int d = (blockIdx.x * blockDim.x + threadIdx.x) >> 5;
    int lane = threadIdx.x & 31;
    if (d >= NS) return;

    float attv[16], xrv[16];
    {
        const float4* pa = (const float4*)(att + lane * 16);
        const float4* pr = (const float4*)(xr + (size_t)d * HC3 + lane * 16);
        #pragma unroll
        for (int q = 0; q < 4; q++) {
            float4 a = pa[q], r = pr[q];
            attv[q*4+0]=a.x; attv[q*4+1]=a.y; attv[q*4+2]=a.z; attv[q*4+3]=a.w;
            xrv[q*4+0]=r.x; xrv[q*4+1]=r.y; xrv[q*4+2]=r.z; xrv[q*4+3]=r.w;
        }
    }
    int b0 = off[d], b1 = off[d + 1];

    float m = -1e30f, den = 0.f, acc[16] = {};
    int s = (b0 < b1) ? srcs[b0] : 0;
    for (int i = b0; i < b1; i++) {
        int s_next = (i + 1 < b1) ? srcs[i + 1] : 0;
        const float4* p = (const float4*)(xl + (size_t)s * HC3 + lane * 16);
        float t[16];
        #pragma unroll
        for (int q = 0; q < 4; q++) {
            float4 tv = p[q];
            t[q*4+0]=tv.x; t[q*4+1]=tv.y; t[q*4+2]=tv.z; t[q*4+3]=tv.w;
        }
        float pp = 0.f;
        #pragma unroll
        for (int v = 0; v < 16; v++) {
            float g = t[v] + xrv[v];
            g = g > 0.f ? g : 0.2f * g;
            pp = fmaf(g, attv[v], pp);
        }
        pp += __shfl_xor_sync(0xFFFFFFFFu, pp, 1);
        pp += __shfl_xor_sync(0xFFFFFFFFu, pp, 2);
        pp += __shfl_xor_sync(0xFFFFFFFFu, pp, 4);
        float mn = fmaxf(m, pp);
        float sc = __expf(m - mn);
        float a  = __expf(pp - mn);
        den = den * sc + a;
        #pragma unroll
        for (int v = 0; v < 16; v++) acc[v] = fmaf(acc[v], sc, a * t[v]);
        m = mn;
        s = s_next;
    }

    float inv = 1.f / (den + 1e-16f);
    float ov[16];
    #pragma unroll
    for (int v = 0; v < 16; v++) {
        float hv = acc[v] * inv;
        hv += __shfl_xor_sync(0xFFFFFFFFu, hv, 8);
        hv += __shfl_xor_sync(0xFFFFFFFFu, hv, 16);
        ov[v] = 0.25f * hv;
    }
    if (lane < 8) {
        #pragma unroll
        for (int v = 0; v < 16; v++) {
            int c = lane * 16 + v;
            float x = ov[v] + bias3[c] + sl3[(size_t)d * C3 + c];
            ov[v] = x > 0.f ? x : (__expf(x) - 1.f);
        }
        float4* po = (float4*)(out + (size_t)d * C3 + lane * 16);
        #pragma unroll
        for (int q = 0; q < 4; q++)
            po[q] = make_float4(ov[q*4+0], ov[q*4+1], ov[q*4+2], ov[q*4+3]);
    }
}

// ---------------- host launch ----------------
static inline float* sym(const void* s) {
    void* p = nullptr;
    cudaGetSymbolAddress(&p, s);
    return (float*)p;
}
static inline __half* symh(const void* s) {
    void* p = nullptr;
    cudaGetSymbolAddress(&p, s);
    return (__half*)p;
}
static inline int* symi(const void* s) {
    void* p = nullptr;
    cudaGetSymbolAddress(&p, s);
    return (int*)p;
}

extern "C" void kernel_launch(void* const* d_in, const int* in_sizes, int n_in,
                              void* d_out, int out_size) {
    const float* x_sample = (const float*)d_in[0];
    const float* x_gene   = (const float*)d_in[1];
    const int*   sg_src   = (const int*)d_in[2];
    const int*   sg_dst   = (const int*)d_in[3];
    const int*   gs_src   = (const int*)d_in[4];
    const int*   gs_dst   = (const int*)d_in[5];
    const float* Wl1_sg = (const float*)d_in[6];
    const float* bl1_sg = (const float*)d_in[7];
    const float* Wr1_sg = (const float*)d_in[8];
    const float* br1_sg = (const float*)d_in[9];
    const float* att1_sg  = (const float*)d_in[10];
    const float* bias1_sg = (const float*)d_in[11];
    const float* Wl1_gs = (const float*)d_in[12];
    const float* bl1_gs = (const float*)d_in[13];
    const float* Wr1_gs = (const float*)d_in[14];
    const float* br1_gs = (const float*)d_in[15];
    const float* att1_gs  = (const float*)d_in[16];
    const float* bias1_gs = (const float*)d_in[17];
    const float* Wl3_gs = (const float*)d_in[18];
    const float* bl3_gs = (const float*)d_in[19];
    const float* Wr3_gs = (const float*)d_in[20];
    const float* br3_gs = (const float*)d_in[21];
    const float* att3_gs  = (const float*)d_in[22];
    const float* bias3_gs = (const float*)d_in[23];
    const float* sl1_W = (const float*)d_in[24];
    const float* sl1_b = (const float*)d_in[25];
    const float* sl3_W = (const float*)d_in[26];
    const float* sl3_b = (const float*)d_in[27];
    float* out = (float*)d_out;

    float* xl_sg = sym(g_xl_sg);
    float* xr_sg = sym(g_xr_sg);
    float* xl_gs = sym(g_xl_gs);
    float* xr_gs = sym(g_xr_gs);
    float* sl1 = sym(g_sl1);
    float* xl3 = sym(g_xl3);
    float* xr3 = sym(g_xr3);
    float* sl3 = sym(g_sl3);
    float* b5p = sym(g_b5p);
    __half* hxs = symh(g_hxs);
    __half* hxg = symh(g_hxg);
    __half* hWl1sg = symh(g_hWl1sg);
    __half* hWr1sg = symh(g_hWr1sg);
    __half* hWl1gs = symh(g_hWl1gs);
    __half* hWr1gs = symh(g_hWr1gs);
    __half* hw5 = symh(g_hw5);
    __half* hWl3 = symh(g_hWl3);
    __half* hWr3 = symh(g_hWr3);
    __half* hsl3W = symh(g_hsl3W);
    __half* x1h_gene = symh(g_x1h_gene);
    __half* x1h_sample = symh(g_x1h_sample);
    int* deg_sg = symi(g_deg_sg);
    int* deg_gs = symi(g_deg_gs);
    int* off_sg = symi(g_off_sg);
    int* cur_sg = symi(g_cur_sg);
    int* srcs_sg = symi(g_srcs_sg);
    int* off_gs = symi(g_off_gs);
    int* cur_gs = symi(g_cur_gs);
    int* srcs_gs = symi(g_srcs_gs);

    cudaFuncSetAttribute(gemm_batch, cudaFuncAttributeMaxDynamicSharedMemorySize, GEMM_SMEM);

    dim3 tb(256);
    int eb = (NE + 255) / 256;

    // ----- fork: CSR chain on side stream, concurrent with cvt + gemm batch 1 -----
    cudaStream_t sB;
    cudaStreamCreateWithFlags(&sB, cudaStreamNonBlocking);
    cudaEvent_t evFork, evJoin;
    cudaEventCreateWithFlags(&evFork, cudaEventDisableTiming);
    cudaEventCreateWithFlags(&evJoin, cudaEventDisableTiming);

    cudaEventRecord(evFork, 0);
    cudaStreamWaitEvent(sB, evFork, 0);

    // stream B: CSR build
    cudaMemsetAsync(deg_sg, 0, NG * sizeof(int), sB);
    cudaMemsetAsync(deg_gs, 0, NS * sizeof(int), sB);
    count2_kernel<<<eb, tb, 0, sB>>>(sg_dst, gs_dst, deg_sg, deg_gs);
    scan2_kernel<<<2, 1024, 0, sB>>>(deg_sg, off_sg, cur_sg, deg_gs, off_gs, cur_gs);
    scatter2_kernel<<<eb, tb, 0, sB>>>(sg_src, sg_dst, cur_sg, srcs_sg,
                                       gs_src, gs_dst, cur_gs, srcs_gs);
    cudaEventRecord(evJoin, sB);

    // main stream: fp16 conversion + layer-1 GEMMs
    cvt_all<<<(NG * DIN + 255) / 256, tb>>>(
        x_sample, x_gene, Wl1_sg, Wr1_sg, Wl1_gs, Wr1_gs, sl1_W, sl1_b,
        Wl3_gs, Wr3_gs, sl3_W,
        hxs, hxg, hWl1sg, hWr1sg, hWl1gs, hWr1gs, hw5, b5p, hWl3, hWr3, hsl3W);

    const int MB_NS = NS / 128;            // 32
    const int MB_NG = (NG + 127) / 128;    // 157

    {
        GemmBatch P;
        int blk = 0;
        P.seg[0] = {hxs, hWl1sg, bl1_sg, xl_sg, HC1, NS, HC1, 2, blk}; blk += 2 * MB_NS;
        P.seg[1] = {hxg, hWr1sg, br1_sg, xr_sg, HC1, NG, HC1, 2, blk}; blk += 2 * MB_NG;
        P.seg[2] = {hxg, hWl1gs, bl1_gs, xl_gs, HC1, NG, HC1, 2, blk}; blk += 2 * MB_NG;
        P.seg[3] = {hxs, hWr1gs, br1_gs, xr_gs, HC1, NS, HC1, 2, blk}; blk += 2 * MB_NS;
        P.seg[4] = {hxs, hw5,    b5p,    sl1,   128, NS, C1,  1, blk}; blk += MB_NS;
        P.seg[5] = P.seg[4];
        P.nseg = 5;
        gemm_batch<<<blk, GEMM_THREADS, GEMM_SMEM>>>(P);
    }

    // join: gat1 needs both GEMM outputs and CSR
    cudaStreamWaitEvent(0, evJoin, 0);

    gat1_dual<<<((NG + NS) * 32 + 255) / 256, tb>>>(
        off_sg, srcs_sg, xl_sg, xr_sg, att1_sg, bias1_sg, x1h_gene,
        off_gs, srcs_gs, xl_gs, xr_gs, att1_gs, bias1_gs, sl1, x1h_sample);

    {
        GemmBatch P;
        int blk = 0;
        P.seg[0] = {x1h_gene,   hWl3,  bl3_gs, xl3, HC3, NG, HC3, 4, blk}; blk += 4 * MB_NG;
        P.seg[1] = {x1h_sample, hWr3,  br3_gs, xr3, HC3, NS, HC3, 4, blk}; blk += 4 * MB_NS;
        P.seg[2] = {x1h_sample, hsl3W, sl3_b,  sl3, C3,  NS, C3,  1, blk}; blk += MB_NS;
        P.seg[3] = P.seg[2];
        P.seg[4] = P.seg[2];
        P.seg[5] = P.seg[2];
        P.nseg = 3;
        gemm_batch<<<blk, GEMM_THREADS, GEMM_SMEM>>>(P);
    }

    gat3_warp<<<(NS * 32 + 255) / 256, tb>>>(off_gs, srcs_gs, xl3, xr3, att3_gs, bias3_gs, sl3, out);
}

// round 14
// speedup vs baseline: 1.1240x; 1.1240x over previous
#include <cuda_runtime.h>
#include <cuda_fp16.h>
#include <mma.h>
#include <math.h>
#include <stddef.h>
#include <stdint.h>

using namespace nvcuda;

// ---------------- problem constants ----------------
#define NS   4096
#define NG   20000
#define NGP  20096
#define NE   131072
#define DIN  256
#define H    4
#define C1   64
#define C3   128
#define HC1  256
#define HC3  512

// ---------------- device scratch (all GEMM outputs fp16) ----------------
__device__ __align__(128) __half g_xl_sg[NS * HC1];
__device__ __align__(128) __half g_xr_sg[NGP * HC1];
__device__ __align__(128) __half g_xl_gs[NGP * HC1];
__device__ __align__(128) __half g_xr_gs[NS * HC1];
__device__ __align__(128) __half g_sl1[NS * C1];
__device__ __align__(128) __half g_xl3[NGP * HC3];
__device__ __align__(128) __half g_xr3[NS * HC3];
__device__ __align__(128) __half g_sl3[NS * C3];
__device__ __align__(128) float  g_b5p[128];

__device__ __align__(128) __half g_hxs[NS * DIN];
__device__ __align__(128) __half g_hxg[NG * DIN];
__device__ __align__(128) __half g_hWl1sg[DIN * HC1];
__device__ __align__(128) __half g_hWr1sg[DIN * HC1];
__device__ __align__(128) __half g_hWl1gs[DIN * HC1];
__device__ __align__(128) __half g_hWr1gs[DIN * HC1];
__device__ __align__(128) __half g_hw5[DIN * 128];
__device__ __align__(128) __half g_hWl3[DIN * HC3];
__device__ __align__(128) __half g_hWr3[DIN * HC3];
__device__ __align__(128) __half g_hsl3W[DIN * C3];
__device__ __align__(128) __half g_x1h_gene[NG * HC1];
__device__ __align__(128) __half g_x1h_sample[NS * HC1];

__device__ int g_deg_sg[NG];
__device__ int g_deg_gs[NS];
__device__ int g_off_sg[NG + 1];
__device__ int g_cur_sg[NG];
__device__ int g_srcs_sg[NE];
__device__ int g_off_gs[NS + 1];
__device__ int g_cur_gs[NS];
__device__ int g_srcs_gs[NE];

// ---------------- helpers ----------------
__device__ __forceinline__ uint32_t smem_u32(const void* p) {
    uint32_t a;
    asm("{ .reg .u64 t; cvta.to.shared.u64 t, %1; cvt.u32.u64 %0, t; }" : "=r"(a) : "l"(p));
    return a;
}
__device__ __forceinline__ uint32_t h2_bits(__half2 h) {
    uint32_t u;
    memcpy(&u, &h, 4);
    return u;
}
#define CP_ASYNC16(dst, src) \
    asm volatile("cp.async.ca.shared.global [%0], [%1], 16;" :: "r"(dst), "l"(src))
#define CP_COMMIT() asm volatile("cp.async.commit_group;")
#define CP_WAIT(n)  asm volatile("cp.async.wait_group %0;" :: "n"(n))

// ---------------- fp32 -> fp16 conversion (pair-vectorized) ----------------
__global__ void cvt_all(const float* __restrict__ xs, const float* __restrict__ xg,
                        const float* __restrict__ Wl1sg, const float* __restrict__ Wr1sg,
                        const float* __restrict__ Wl1gs, const float* __restrict__ Wr1gs,
                        const float* __restrict__ w5, const float* __restrict__ b5,
                        const float* __restrict__ Wl3, const float* __restrict__ Wr3,
                        const float* __restrict__ sl3W,
                        __half* __restrict__ hxs, __half* __restrict__ hxg,
                        __half* __restrict__ hWl1sg, __half* __restrict__ hWr1sg,
                        __half* __restrict__ hWl1gs, __half* __restrict__ hWr1gs,
                        __half* __restrict__ hw5, float* __restrict__ b5p,
                        __half* __restrict__ hWl3, __half* __restrict__ hWr3,
                        __half* __restrict__ hsl3W) {
    int i = blockIdx.x * blockDim.x + threadIdx.x;   // pair index
    if (i < NS * DIN / 2) {
        float2 v = ((const float2*)xs)[i];
        ((__half2*)hxs)[i] = __floats2half2_rn(v.x, v.y);
    }
    if (i < NG * DIN / 2) {
        float2 v = ((const float2*)xg)[i];
        ((__half2*)hxg)[i] = __floats2half2_rn(v.x, v.y);
    }
    if (i < DIN * HC1 / 2) {
        float2 a = ((const float2*)Wl1sg)[i];
        ((__half2*)hWl1sg)[i] = __floats2half2_rn(a.x, a.y);
        float2 b = ((const float2*)Wr1sg)[i];
        ((__half2*)hWr1sg)[i] = __floats2half2_rn(b.x, b.y);
        float2 c = ((const float2*)Wl1gs)[i];
        ((__half2*)hWl1gs)[i] = __floats2half2_rn(c.x, c.y);
        float2 d = ((const float2*)Wr1gs)[i];
        ((__half2*)hWr1gs)[i] = __floats2half2_rn(d.x, d.y);
    }
    if (i < DIN * 128 / 2) {
        int k = i >> 6, c = (i << 1) & 127;          // c even
        __half2 hv;
        if (c < C1) {
            float2 v = ((const float2*)(w5 + k * C1))[c >> 1];
            hv = __floats2half2_rn(v.x, v.y);
        } else {
            hv = __floats2half2_rn(0.f, 0.f);
        }
        ((__half2*)hw5)[i] = hv;
        float2 s = ((const float2*)sl3W)[i];
        ((__half2*)hsl3W)[i] = __floats2half2_rn(s.x, s.y);
    }
    if (i < 128) b5p[i] = (i < C1) ? b5[i] : 0.f;
    if (i < DIN * HC3 / 2) {
        float2 a = ((const float2*)Wl3)[i];
        ((__half2*)hWl3)[i] = __floats2half2_rn(a.x, a.y);
        float2 b = ((const float2*)Wr3)[i];
        ((__half2*)hWr3)[i] = __floats2half2_rn(b.x, b.y);
    }
}

// ---------------- batched fp16 WMMA GEMM (fp32 accum, fp16 output) ----------------
struct GemmSeg {
    const __half* A; const __half* B; const float* bias; __half* C;
    int ldB; int M; int Nout; int nx; int blk0;
};
struct GemmBatch { GemmSeg seg[6]; int nseg; };

#define GEMM_THREADS 256
#define A_PITCH_H 72
#define B_PITCH_H 136
#define A_BUF_B   18432
#define B_BUF_B   17408
#define B_BASE_B  36864
#define GEMM_SMEM 71680

__global__ void __launch_bounds__(GEMM_THREADS) gemm_batch(GemmBatch P) {
    extern __shared__ char smc[];
    const int tid = threadIdx.x;
    const int wid = tid >> 5;
    const int warp_m = wid >> 1;
    const int warp_n = wid & 1;

    GemmSeg g = P.seg[0];
    #pragma unroll
    for (int i = 1; i < 6; i++)
        if (i < P.nseg && (int)blockIdx.x >= P.seg[i].blk0) g = P.seg[i];
    int lb = blockIdx.x - g.blk0;
    const int m0 = (lb / g.nx) * 128;
    const int col0 = (lb % g.nx) * 128;

    wmma::fragment<wmma::accumulator, 16, 16, 16, float> cfr[2][4];
    #pragma unroll
    for (int i = 0; i < 2; i++)
        #pragma unroll
        for (int t = 0; t < 4; t++) wmma::fill_fragment(cfr[i][t], 0.f);

    auto loadA = [&](int s, int b) {
        const __half* Ab = g.A + (size_t)m0 * 256 + s * 64;
        char* dst = smc + b * A_BUF_B;
        #pragma unroll
        for (int i = 0; i < 4; i++) {
            int ch = tid + i * 256;
            int r = ch >> 3, c8 = ch & 7;
            char* dp = dst + r * 144 + c8 * 16;
            if (m0 + r < g.M) {
                CP_ASYNC16(smem_u32(dp), Ab + (size_t)r * 256 + c8 * 8);
            } else {
                *(uint4*)dp = make_uint4(0, 0, 0, 0);
            }
        }
    };
    auto loadB = [&](int s, int b) {
        const __half* Bb = g.B + (size_t)(s * 64) * g.ldB + col0;
        char* dst = smc + B_BASE_B + b * B_BUF_B;
        #pragma unroll
        for (int i = 0; i < 4; i++) {
            int ch = tid + i * 256;
            int r = ch >> 4, c8 = ch & 15;
            CP_ASYNC16(smem_u32(dst + r * 272 + c8 * 16), Bb + (size_t)r * g.ldB + c8 * 8);
        }
    };

    loadA(0, 0); loadB(0, 0);
    CP_COMMIT();

    #pragma unroll 1
    for (int s = 0; s < 4; s++) {
        int b = s & 1;
        if (s < 3) { loadA(s + 1, b ^ 1); loadB(s + 1, b ^ 1); CP_COMMIT(); }
        if (s < 3) { CP_WAIT(1); } else { CP_WAIT(0); }
        __syncthreads();

        const __half* As = (const __half*)(smc + b * A_BUF_B) + warp_m * 32 * A_PITCH_H;
        const __half* Bs = (const __half*)(smc + B_BASE_B + b * B_BUF_B);
        #pragma unroll
        for (int kk = 0; kk < 4; kk++) {
            wmma::fragment<wmma::matrix_a, 16, 16, 16, __half, wmma::row_major> af[2];
            wmma::load_matrix_sync(af[0], As + kk * 16, A_PITCH_H);
            wmma::load_matrix_sync(af[1], As + 16 * A_PITCH_H + kk * 16, A_PITCH_H);
            #pragma unroll
            for (int t = 0; t < 4; t++) {
                wmma::fragment<wmma::matrix_b, 16, 16, 16, __half, wmma::row_major> bf;
                wmma::load_matrix_sync(bf, Bs + kk * 16 * B_PITCH_H + warp_n * 64 + t * 16, B_PITCH_H);
                wmma::mma_sync(cfr[0][t], af[0], bf, cfr[0][t]);
                wmma::mma_sync(cfr[1][t], af[1], bf, cfr[1][t]);
            }
        }
        __syncthreads();
    }

    float* stg = (float*)smc;
    #pragma unroll
    for (int i = 0; i < 2; i++)
        #pragma unroll
        for (int t = 0; t < 4; t++)
            wmma::store_matrix_sync(stg + (warp_m * 32 + i * 16) * 132 + warp_n * 64 + t * 16,
                                    cfr[i][t], 132, wmma::mem_row_major);
    __syncthreads();

    #pragma unroll
    for (int id = tid; id < 128 * 32; id += 256) {
        int r = id >> 5;
        int c = (id & 31) * 4;
        if (col0 + c < g.Nout) {
            float4 v = *(const float4*)(stg + r * 132 + c);
            float4 bv = *(const float4*)(g.bias + col0 + c);
            __half2 h0 = __floats2half2_rn(v.x + bv.x, v.y + bv.y);
            __half2 h1 = __floats2half2_rn(v.z + bv.z, v.w + bv.w);
            uint2 pk = make_uint2(h2_bits(h0), h2_bits(h1));
            *(uint2*)(g.C + (size_t)(m0 + r) * g.Nout + col0 + c) = pk;
        }
    }
}

// ---------------- CSR build ----------------
__global__ void count2_kernel(const int* __restrict__ sg_dst, const int* __restrict__ gs_dst,
                              int* __restrict__ dsg, int* __restrict__ dgs) {
    int e = blockIdx.x * blockDim.x + threadIdx.x;
    if (e < NE) {
        atomicAdd(&dsg[sg_dst[e]], 1);
        atomicAdd(&dgs[gs_dst[e]], 1);
    }
}

__global__ void scan2_kernel(const int* __restrict__ dsg, int* __restrict__ off_sg, int* __restrict__ cur_sg,
                             const int* __restrict__ dgs, int* __restrict__ off_gs, int* __restrict__ cur_gs) {
    const int* deg = (blockIdx.x == 0) ? dsg : dgs;
    int* off = (blockIdx.x == 0) ? off_sg : off_gs;
    int* cur = (blockIdx.x == 0) ? cur_sg : cur_gs;
    const int n  = (blockIdx.x == 0) ? NG : NS;
    const int ch = (blockIdx.x == 0) ? 20 : 4;
    __shared__ int wsum[32];
    int tid = threadIdx.x, lane = tid & 31, wid = tid >> 5;
    int base = tid * ch;

    int vals[20];
    int tsum = 0;
    #pragma unroll 20
    for (int j = 0; j < 20; j++) {
        if (j < ch) {
            int i = base + j;
            int v = (i < n) ? deg[i] : 0;
            vals[j] = tsum;
            tsum += v;
        }
    }
    int x = tsum;
    #pragma unroll
    for (int o = 1; o < 32; o <<= 1) {
        int t = __shfl_up_sync(0xFFFFFFFFu, x, o);
        if (lane >= o) x += t;
    }
    if (lane == 31) wsum[wid] = x;
    __syncthreads();
    if (wid == 0) {
        int y = wsum[lane];
        #pragma unroll
        for (int o = 1; o < 32; o <<= 1) {
            int t = __shfl_up_sync(0xFFFFFFFFu, y, o);
            if (lane >= o) y += t;
        }
        wsum[lane] = y;
    }
    __syncthreads();
    int pre = (wid > 0) ? wsum[wid - 1] : 0;
    int tbase = pre + x - tsum;

    #pragma unroll 20
    for (int j = 0; j < 20; j++) {
        if (j < ch) {
            int i = base + j;
            if (i < n) {
                int e = tbase + vals[j];
                off[i] = e;
                cur[i] = e;
            }
        }
    }
    if (tid == 0) off[n] = wsum[31];
}

__global__ void scatter2_kernel(const int* __restrict__ sg_src, const int* __restrict__ sg_dst,
                                int* __restrict__ cur_sg, int* __restrict__ srcs_sg,
                                const int* __restrict__ gs_src, const int* __restrict__ gs_dst,
                                int* __restrict__ cur_gs, int* __restrict__ srcs_gs) {
    int e = blockIdx.x * blockDim.x + threadIdx.x;
    if (e < NE) {
        int p = atomicAdd(&cur_sg[sg_dst[e]], 1);
        srcs_sg[p] = sg_src[e];
        int q = atomicAdd(&cur_gs[gs_dst[e]], 1);
        srcs_gs[q] = gs_src[e];
    }
}

// ---------------- layer-1 GAT core: warp per dst, fp16 tables ----------------
__device__ __forceinline__ void gat1_core(int d, int lane,
                                          const int* __restrict__ off, const int* __restrict__ srcs,
                                          const __half* __restrict__ xl, const __half* __restrict__ xr,
                                          const float* __restrict__ att, const float* __restrict__ bias,
                                          const __half* __restrict__ self, __half* __restrict__ out) {
    float attv[8], xrv[8];
    {
        const float4* pa = (const float4*)(att + lane * 8);
        float4 a0 = pa[0], a1 = pa[1];
        attv[0]=a0.x; attv[1]=a0.y; attv[2]=a0.z; attv[3]=a0.w;
        attv[4]=a1.x; attv[5]=a1.y; attv[6]=a1.z; attv[7]=a1.w;
        uint4 rr = *(const uint4*)(xr + (size_t)d * HC1 + lane * 8);
        const __half2* rh = (const __half2*)&rr;
        #pragma unroll
        for (int j = 0; j < 4; j++) {
            float2 f = __half22float2(rh[j]);
            xrv[2*j] = f.x; xrv[2*j+1] = f.y;
        }
    }
    int b0 = off[d], b1 = off[d + 1];

    float m = -1e30f, den = 0.f, acc[8] = {};
    int s = (b0 < b1) ? srcs[b0] : 0;
    for (int i = b0; i < b1; i++) {
        int s_next = (i + 1 < b1) ? srcs[i + 1] : 0;
        uint4 tt = *(const uint4*)(xl + (size_t)s * HC1 + lane * 8);
        const __half2* th = (const __half2*)&tt;
        float t[8];
        #pragma unroll
        for (int j = 0; j < 4; j++) {
            float2 f = __half22float2(th[j]);
            t[2*j] = f.x; t[2*j+1] = f.y;
        }
        float pp = 0.f;
        #pragma unroll
        for (int v = 0; v < 8; v++) {
            float g = t[v] + xrv[v];
            g = g > 0.f ? g : 0.2f * g;
            pp = fmaf(g, attv[v], pp);
        }
        pp += __shfl_xor_sync(0xFFFFFFFFu, pp, 1);
        pp += __shfl_xor_sync(0xFFFFFFFFu, pp, 2);
        pp += __shfl_xor_sync(0xFFFFFFFFu, pp, 4);
        float mn = fmaxf(m, pp);
        float sc = __expf(m - mn);
        float a  = __expf(pp - mn);
        den = den * sc + a;
        #pragma unroll
        for (int v = 0; v < 8; v++) acc[v] = fmaf(acc[v], sc, a * t[v]);
        m = mn;
        s = s_next;
    }

    float sv[8] = {};
    if (self) {
        uint4 ss = *(const uint4*)(self + (size_t)d * C1 + (lane & 7) * 8);
        const __half2* sh = (const __half2*)&ss;
        #pragma unroll
        for (int j = 0; j < 4; j++) {
            float2 f = __half22float2(sh[j]);
            sv[2*j] = f.x; sv[2*j+1] = f.y;
        }
    }

    float inv = 1.f / (den + 1e-16f);
    __half2 hv[4];
    #pragma unroll
    for (int j = 0; j < 4; j++) {
        float x0 = acc[2*j]   * inv + bias[lane * 8 + 2*j]   + sv[2*j];
        float x1 = acc[2*j+1] * inv + bias[lane * 8 + 2*j+1] + sv[2*j+1];
        x0 = x0 > 0.f ? x0 : (__expf(x0) - 1.f);
        x1 = x1 > 0.f ? x1 : (__expf(x1) - 1.f);
        hv[j] = __floats2half2_rn(x0, x1);
    }
    *(uint4*)(out + (size_t)d * HC1 + lane * 8) = *(uint4*)hv;
}

__global__ void gat1_dual(const int* __restrict__ off_sg, const int* __restrict__ srcs_sg,
                          const __half* __restrict__ xl_sg, const __half* __restrict__ xr_sg,
                          const float* __restrict__ att_sg, const float* __restrict__ bias_sg,
                          __half* __restrict__ out_sg,
                          const int* __restrict__ off_gs, const int* __restrict__ srcs_gs,
                          const __half* __restrict__ xl_gs, const __half* __restrict__ xr_gs,
                          const float* __restrict__ att_gs, const float* __restrict__ bias_gs,
                          const __half* __restrict__ self_gs, __half* __restrict__ out_gs) {
    int w = (blockIdx.x * blockDim.x + threadIdx.x) >> 5;
    int lane = threadIdx.x & 31;
    if (w < NG) {
        gat1_core(w, lane, off_sg, srcs_sg, xl_sg, xr_sg, att_sg, bias_sg, nullptr, out_sg);
    } else if (w < NG + NS) {
        gat1_core(w - NG, lane, off_gs, srcs_gs, xl_gs, xr_gs, att_gs, bias_gs, self_gs, out_gs);
    }
}

// ---------------- layer-3 GAT: warp per dst, fp16 tables, head mean ----------------
__global__ void gat3_warp(const int* __restrict__ off, const int* __restrict__ srcs,
                          const __half* __restrict__ xl, const __half* __restrict__ xr,
                          const float* __restrict__ att, const float* __restrict__ bias3,
                          const __half* __restrict__ sl3, float* __restrict__ out) {
    int d = (blockIdx.x * blockDim.x + threadIdx.x) >> 5;
    int lane = threadIdx.x & 31;
    if (d >= NS) return;

    float attv[16], xrv[16];
    {
        const float4* pa = (const float4*)(att + lane * 16);
        #pragma unroll
        for (int q = 0; q < 4; q++) {
            float4 a = pa[q];
            attv[q*4+0]=a.x; attv[q*4+1]=a.y; attv[q*4+2]=a.z; attv[q*4+3]=a.w;
        }
        uint4 r0 = *(const uint4*)(xr + (size_t)d * HC3 + lane * 16);
        uint4 r1 = *(const uint4*)(xr + (size_t)d * HC3 + lane * 16 + 8);
        const __half2* rh0 = (const __half2*)&r0;
        const __half2* rh1 = (const __half2*)&r1;
        #pragma unroll
        for (int j = 0; j < 4; j++) {
            float2 f0 = __half22float2(rh0[j]);
            float2 f1 = __half22float2(rh1[j]);
            xrv[2*j] = f0.x; xrv[2*j+1] = f0.y;
            xrv[8+2*j] = f1.x; xrv[8+2*j+1] = f1.y;
        }
    }
    int b0 = off[d], b1 = off[d + 1];

    float m = -1e30f, den = 0.f, acc[16] = {};
    int s = (b0 < b1) ? srcs[b0] : 0;
    for (int i = b0; i < b1; i++) {
        int s_next = (i + 1 < b1) ? srcs[i + 1] : 0;
        uint4 t0 = *(const uint4*)(xl + (size_t)s * HC3 + lane * 16);
        uint4 t1 = *(const uint4*)(xl + (size_t)s * HC3 + lane * 16 + 8);
        const __half2* th0 = (const __half2*)&t0;
        const __half2* th1 = (const __half2*)&t1;
        float t[16];
        #pragma unroll
        for (int j = 0; j < 4; j++) {
            float2 f0 = __half22float2(th0[j]);
            float2 f1 = __half22float2(th1[j]);
            t[2*j] = f0.x; t[2*j+1] = f0.y;
            t[8+2*j] = f1.x; t[8+2*j+1] = f1.y;
        }
        float pp = 0.f;
        #pragma unroll
        for (int v = 0; v < 16; v++) {
            float g = t[v] + xrv[v];
            g = g > 0.f ? g : 0.2f * g;
            pp = fmaf(g, attv[v], pp);
        }
        pp += __shfl_xor_sync(0xFFFFFFFFu, pp, 1);
        pp += __shfl_xor_sync(0xFFFFFFFFu, pp, 2);
        pp += __shfl_xor_sync(0xFFFFFFFFu, pp, 4);
        float mn = fmaxf(m, pp);
        float sc = __expf(m - mn);
        float a  = __expf(pp - mn);
        den = den * sc + a;
        #pragma unroll
        for (int v = 0; v < 16; v++) acc[v] = fmaf(acc[v], sc, a * t[v]);
        m = mn;
        s = s_next;
    }

    float inv = 1.f / (den + 1e-16f);
    float ov[16];
    #pragma unroll
    for (int v = 0; v < 16; v++) {
        float hv = acc[v] * inv;
        hv += __shfl_xor_sync(0xFFFFFFFFu, hv, 8);
        hv += __shfl_xor_sync(0xFFFFFFFFu, hv, 16);
        ov[v] = 0.25f * hv;
    }
    if (lane < 8) {
        uint4 s0 = *(const uint4*)(sl3 + (size_t)d * C3 + lane * 16);
        uint4 s1 = *(const uint4*)(sl3 + (size_t)d * C3 + lane * 16 + 8);
        const __half2* sh0 = (const __half2*)&s0;
        const __half2* sh1 = (const __half2*)&s1;
        float sv[16];
        #pragma unroll
        for (int j = 0; j < 4; j++) {
            float2 f0 = __half22float2(sh0[j]);
            float2 f1 = __half22float2(sh1[j]);
            sv[2*j] = f0.x; sv[2*j+1] = f0.y;
            sv[8+2*j] = f1.x; sv[8+2*j+1] = f1.y;
        }
        #pragma unroll
        for (int v = 0; v < 16; v++) {
            int c = lane * 16 + v;
            float x = ov[v] + bias3[c] + sv[v];
            ov[v] = x > 0.f ? x : (__expf(x) - 1.f);
        }
        float4* po = (float4*)(out + (size_t)d * C3 + lane * 16);
        #pragma unroll
        for (int q = 0; q < 4; q++)
            po[q] = make_float4(ov[q*4+0], ov[q*4+1], ov[q*4+2], ov[q*4+3]);
    }
}

// ---------------- host launch ----------------
static inline __half* symh(const void* s) {
    void* p = nullptr;
    cudaGetSymbolAddress(&p, s);
    return (__half*)p;
}
static inline float* symf(const void* s) {
    void* p = nullptr;
    cudaGetSymbolAddress(&p, s);
    return (float*)p;
}
static inline int* symi(const void* s) {
    void* p = nullptr;
    cudaGetSymbolAddress(&p, s);
    return (int*)p;
}

extern "C" void kernel_launch(void* const* d_in, const int* in_sizes, int n_in,
                              void* d_out, int out_size) {
    const float* x_sample = (const float*)d_in[0];
    const float* x_gene   = (const float*)d_in[1];
    const int*   sg_src   = (const int*)d_in[2];
    const int*   sg_dst   = (const int*)d_in[3];
    const int*   gs_src   = (const int*)d_in[4];
    const int*   gs_dst   = (const int*)d_in[5];
    const float* Wl1_sg = (const float*)d_in[6];
    const float* bl1_sg = (const float*)d_in[7];
    const float* Wr1_sg = (const float*)d_in[8];
    const float* br1_sg = (const float*)d_in[9];
    const float* att1_sg  = (const float*)d_in[10];
    const float* bias1_sg = (const float*)d_in[11];
    const float* Wl1_gs = (const float*)d_in[12];
    const float* bl1_gs = (const float*)d_in[13];
    const float* Wr1_gs = (const float*)d_in[14];
    const float* br1_gs = (const float*)d_in[15];
    const float* att1_gs  = (const float*)d_in[16];
    const float* bias1_gs = (const float*)d_in[17];
    const float* Wl3_gs = (const float*)d_in[18];
    const float* bl3_gs = (const float*)d_in[19];
    const float* Wr3_gs = (const float*)d_in[20];
    const float* br3_gs = (const float*)d_in[21];
    const float* att3_gs  = (const float*)d_in[22];
    const float* bias3_gs = (const float*)d_in[23];
    const float* sl1_W = (const float*)d_in[24];
    const float* sl1_b = (const float*)d_in[25];
    const float* sl3_W = (const float*)d_in[26];
    const float* sl3_b = (const float*)d_in[27];
    float* out = (float*)d_out;

    __half* xl_sg = symh(g_xl_sg);
    __half* xr_sg = symh(g_xr_sg);
    __half* xl_gs = symh(g_xl_gs);
    __half* xr_gs = symh(g_xr_gs);
    __half* sl1 = symh(g_sl1);
    __half* xl3 = symh(g_xl3);
    __half* xr3 = symh(g_xr3);
    __half* sl3 = symh(g_sl3);
    float* b5p = symf(g_b5p);
    __half* hxs = symh(g_hxs);
    __half* hxg = symh(g_hxg);
    __half* hWl1sg = symh(g_hWl1sg);
    __half* hWr1sg = symh(g_hWr1sg);
    __half* hWl1gs = symh(g_hWl1gs);
    __half* hWr1gs = symh(g_hWr1gs);
    __half* hw5 = symh(g_hw5);
    __half* hWl3 = symh(g_hWl3);
    __half* hWr3 = symh(g_hWr3);
    __half* hsl3W = symh(g_hsl3W);
    __half* x1h_gene = symh(g_x1h_gene);
    __half* x1h_sample = symh(g_x1h_sample);
    int* deg_sg = symi(g_deg_sg);
    int* deg_gs = symi(g_deg_gs);
    int* off_sg = symi(g_off_sg);
    int* cur_sg = symi(g_cur_sg);
    int* srcs_sg = symi(g_srcs_sg);
    int* off_gs = symi(g_off_gs);
    int* cur_gs = symi(g_cur_gs);
    int* srcs_gs = symi(g_srcs_gs);

    cudaFuncSetAttribute(gemm_batch, cudaFuncAttributeMaxDynamicSharedMemorySize, GEMM_SMEM);

    dim3 tb(256);
    int eb = (NE + 255) / 256;

    // ----- fork: CSR chain on side stream -----
    cudaStream_t sB;
    cudaStreamCreateWithFlags(&sB, cudaStreamNonBlocking);
    cudaEvent_t evFork, evJoin;
    cudaEventCreateWithFlags(&evFork, cudaEventDisableTiming);
    cudaEventCreateWithFlags(&evJoin, cudaEventDisableTiming);

    cudaEventRecord(evFork, 0);
    cudaStreamWaitEvent(sB, evFork, 0);

    cudaMemsetAsync(deg_sg, 0, NG * sizeof(int), sB);
    cudaMemsetAsync(deg_gs, 0, NS * sizeof(int), sB);
    count2_kernel<<<eb, tb, 0, sB>>>(sg_dst, gs_dst, deg_sg, deg_gs);
    scan2_kernel<<<2, 1024, 0, sB>>>(deg_sg, off_sg, cur_sg, deg_gs, off_gs, cur_gs);
    scatter2_kernel<<<eb, tb, 0, sB>>>(sg_src, sg_dst, cur_sg, srcs_sg,
                                       gs_src, gs_dst, cur_gs, srcs_gs);
    cudaEventRecord(evJoin, sB);

    // main stream: conversion + layer-1 GEMMs
    cvt_all<<<(NG * DIN / 2 + 255) / 256, tb>>>(
        x_sample, x_gene, Wl1_sg, Wr1_sg, Wl1_gs, Wr1_gs, sl1_W, sl1_b,
        Wl3_gs, Wr3_gs, sl3_W,
        hxs, hxg, hWl1sg, hWr1sg, hWl1gs, hWr1gs, hw5, b5p, hWl3, hWr3, hsl3W);

    const int MB_NS = NS / 128;            // 32
    const int MB_NG = (NG + 127) / 128;    // 157

    {
        GemmBatch P;
        int blk = 0;
        P.seg[0] = {hxs, hWl1sg, bl1_sg, xl_sg, HC1, NS, HC1, 2, blk}; blk += 2 * MB_NS;
        P.seg[1] = {hxg, hWr1sg, br1_sg, xr_sg, HC1, NG, HC1, 2, blk}; blk += 2 * MB_NG;
        P.seg[2] = {hxg, hWl1gs, bl1_gs, xl_gs, HC1, NG, HC1, 2, blk}; blk += 2 * MB_NG;
        P.seg[3] = {hxs, hWr1gs, br1_gs, xr_gs, HC1, NS, HC1, 2, blk}; blk += 2 * MB_NS;
        P.seg[4] = {hxs, hw5,    b5p,    sl1,   128, NS, C1,  1, blk}; blk += MB_NS;
        P.seg[5] = P.seg[4];
        P.nseg = 5;
        gemm_batch<<<blk, GEMM_THREADS, GEMM_SMEM>>>(P);
    }

    cudaStreamWaitEvent(0, evJoin, 0);

    gat1_dual<<<((NG + NS) * 32 + 255) / 256, tb>>>(
        off_sg, srcs_sg, xl_sg, xr_sg, att1_sg, bias1_sg, x1h_gene,
        off_gs, srcs_gs, xl_gs, xr_gs, att1_gs, bias1_gs, sl1, x1h_sample);

    {
        GemmBatch P;
        int blk = 0;
        P.seg[0] = {x1h_gene,   hWl3,  bl3_gs, xl3, HC3, NG, HC3, 4, blk}; blk += 4 * MB_NG;
        P.seg[1] = {x1h_sample, hWr3,  br3_gs, xr3, HC3, NS, HC3, 4, blk}; blk += 4 * MB_NS;
        P.seg[2] = {x1h_sample, hsl3W, sl3_b,  sl3, C3,  NS, C3,  1, blk}; blk += MB_NS;
        P.seg[3] = P.seg[2];
        P.seg[4] = P.seg[2];
        P.seg[5] = P.seg[2];
        P.nseg = 3;
        gemm_batch<<<blk, GEMM_THREADS, GEMM_SMEM>>>(P);
    }

    gat3_warp<<<(NS * 32 + 255) / 256, tb>>>(off_gs, srcs_gs, xl3, xr3, att3_gs, bias3_gs, sl3, out);
}

// round 15
// speedup vs baseline: 1.1361x; 1.0108x over previous
#include <cuda_runtime.h>
#include <cuda_fp16.h>
#include <mma.h>
#include <math.h>
#include <stddef.h>
#include <stdint.h>

using namespace nvcuda;

// ---------------- problem constants ----------------
#define NS   4096
#define NG   20000
#define NGP  20096
#define NE   131072
#define DIN  256
#define H    4
#define C1   64
#define C3   128
#define HC1  256
#define HC3  512

// ---------------- device scratch (all GEMM outputs fp16) ----------------
__device__ __align__(128) __half g_xl_sg[NS * HC1];
__device__ __align__(128) __half g_xr_sg[NGP * HC1];
__device__ __align__(128) __half g_xl_gs[NGP * HC1];
__device__ __align__(128) __half g_xr_gs[NS * HC1];
__device__ __align__(128) __half g_sl1[NS * C1];
__device__ __align__(128) __half g_xl3[NGP * HC3];
__device__ __align__(128) __half g_xr3[NS * HC3];
__device__ __align__(128) __half g_sl3[NS * C3];
__device__ __align__(128) float  g_b5p[128];

__device__ __align__(128) __half g_hxs[NS * DIN];
__device__ __align__(128) __half g_hxg[NG * DIN];
__device__ __align__(128) __half g_hWl1sg[DIN * HC1];
__device__ __align__(128) __half g_hWr1sg[DIN * HC1];
__device__ __align__(128) __half g_hWl1gs[DIN * HC1];
__device__ __align__(128) __half g_hWr1gs[DIN * HC1];
__device__ __align__(128) __half g_hw5[DIN * 128];
__device__ __align__(128) __half g_hWl3[DIN * HC3];
__device__ __align__(128) __half g_hWr3[DIN * HC3];
__device__ __align__(128) __half g_hsl3W[DIN * C3];
__device__ __align__(128) __half g_x1h_gene[NG * HC1];
__device__ __align__(128) __half g_x1h_sample[NS * HC1];

__device__ int g_deg_sg[NG];
__device__ int g_deg_gs[NS];
__device__ int g_off_sg[NG + 1];
__device__ int g_cur_sg[NG];
__device__ int g_srcs_sg[NE];
__device__ int g_off_gs[NS + 1];
__device__ int g_cur_gs[NS];
__device__ int g_srcs_gs[NE];

// ---------------- helpers ----------------
__device__ __forceinline__ uint32_t smem_u32(const void* p) {
    uint32_t a;
    asm("{ .reg .u64 t; cvta.to.shared.u64 t, %1; cvt.u32.u64 %0, t; }" : "=r"(a) : "l"(p));
    return a;
}
__device__ __forceinline__ uint32_t h2_bits(__half2 h) {
    uint32_t u;
    memcpy(&u, &h, 4);
    return u;
}
#define CP_ASYNC16(dst, src) \
    asm volatile("cp.async.ca.shared.global [%0], [%1], 16;" :: "r"(dst), "l"(src))
#define CP_COMMIT() asm volatile("cp.async.commit_group;")
#define CP_WAIT(n)  asm volatile("cp.async.wait_group %0;" :: "n"(n))

// ---------------- fp32 -> fp16 conversion (pair-vectorized) ----------------
__global__ void cvt_all(const float* __restrict__ xs, const float* __restrict__ xg,
                        const float* __restrict__ Wl1sg, const float* __restrict__ Wr1sg,
                        const float* __restrict__ Wl1gs, const float* __restrict__ Wr1gs,
                        const float* __restrict__ w5, const float* __restrict__ b5,
                        const float* __restrict__ Wl3, const float* __restrict__ Wr3,
                        const float* __restrict__ sl3W,
                        __half* __restrict__ hxs, __half* __restrict__ hxg,
                        __half* __restrict__ hWl1sg, __half* __restrict__ hWr1sg,
                        __half* __restrict__ hWl1gs, __half* __restrict__ hWr1gs,
                        __half* __restrict__ hw5, float* __restrict__ b5p,
                        __half* __restrict__ hWl3, __half* __restrict__ hWr3,
                        __half* __restrict__ hsl3W) {
    int i = blockIdx.x * blockDim.x + threadIdx.x;   // pair index
    if (i < NS * DIN / 2) {
        float2 v = ((const float2*)xs)[i];
        ((__half2*)hxs)[i] = __floats2half2_rn(v.x, v.y);
    }
    if (i < NG * DIN / 2) {
        float2 v = ((const float2*)xg)[i];
        ((__half2*)hxg)[i] = __floats2half2_rn(v.x, v.y);
    }
    if (i < DIN * HC1 / 2) {
        float2 a = ((const float2*)Wl1sg)[i];
        ((__half2*)hWl1sg)[i] = __floats2half2_rn(a.x, a.y);
        float2 b = ((const float2*)Wr1sg)[i];
        ((__half2*)hWr1sg)[i] = __floats2half2_rn(b.x, b.y);
        float2 c = ((const float2*)Wl1gs)[i];
        ((__half2*)hWl1gs)[i] = __floats2half2_rn(c.x, c.y);
        float2 d = ((const float2*)Wr1gs)[i];
        ((__half2*)hWr1gs)[i] = __floats2half2_rn(d.x, d.y);
    }
    if (i < DIN * 128 / 2) {
        int k = i >> 6, c = (i << 1) & 127;          // c even
        __half2 hv;
        if (c < C1) {
            float2 v = ((const float2*)(w5 + k * C1))[c >> 1];
            hv = __floats2half2_rn(v.x, v.y);
        } else {
            hv = __floats2half2_rn(0.f, 0.f);
        }
        ((__half2*)hw5)[i] = hv;
        float2 s = ((const float2*)sl3W)[i];
        ((__half2*)hsl3W)[i] = __floats2half2_rn(s.x, s.y);
    }
    if (i < 128) b5p[i] = (i < C1) ? b5[i] : 0.f;
    if (i < DIN * HC3 / 2) {
        float2 a = ((const float2*)Wl3)[i];
        ((__half2*)hWl3)[i] = __floats2half2_rn(a.x, a.y);
        float2 b = ((const float2*)Wr3)[i];
        ((__half2*)hWr3)[i] = __floats2half2_rn(b.x, b.y);
    }
}

// ---------------- batched fp16 WMMA GEMM (fp32 accum, fp16 output) ----------------
struct GemmSeg {
    const __half* A; const __half* B; const float* bias; __half* C;
    int ldB; int M; int Nout; int nx; int blk0;
};
struct GemmBatch { GemmSeg seg[6]; int nseg; };

#define GEMM_THREADS 256
#define A_PITCH_H 72
#define B_PITCH_H 136
#define A_BUF_B   18432
#define B_BUF_B   17408
#define B_BASE_B  36864
#define GEMM_SMEM 71680

__global__ void __launch_bounds__(GEMM_THREADS) gemm_batch(GemmBatch P) {
    extern __shared__ char smc[];
    const int tid = threadIdx.x;
    const int wid = tid >> 5;
    const int warp_m = wid >> 1;
    const int warp_n = wid & 1;

    GemmSeg g = P.seg[0];
    #pragma unroll
    for (int i = 1; i < 6; i++)
        if (i < P.nseg && (int)blockIdx.x >= P.seg[i].blk0) g = P.seg[i];
    int lb = blockIdx.x - g.blk0;
    const int m0 = (lb / g.nx) * 128;
    const int col0 = (lb % g.nx) * 128;

    wmma::fragment<wmma::accumulator, 16, 16, 16, float> cfr[2][4];
    #pragma unroll
    for (int i = 0; i < 2; i++)
        #pragma unroll
        for (int t = 0; t < 4; t++) wmma::fill_fragment(cfr[i][t], 0.f);

    auto loadA = [&](int s, int b) {
        const __half* Ab = g.A + (size_t)m0 * 256 + s * 64;
        char* dst = smc + b * A_BUF_B;
        #pragma unroll
        for (int i = 0; i < 4; i++) {
            int ch = tid + i * 256;
            int r = ch >> 3, c8 = ch & 7;
            char* dp = dst + r * 144 + c8 * 16;
            if (m0 + r < g.M) {
                CP_ASYNC16(smem_u32(dp), Ab + (size_t)r * 256 + c8 * 8);
            } else {
                *(uint4*)dp = make_uint4(0, 0, 0, 0);
            }
        }
    };
    auto loadB = [&](int s, int b) {
        const __half* Bb = g.B + (size_t)(s * 64) * g.ldB + col0;
        char* dst = smc + B_BASE_B + b * B_BUF_B;
        #pragma unroll
        for (int i = 0; i < 4; i++) {
            int ch = tid + i * 256;
            int r = ch >> 4, c8 = ch & 15;
            CP_ASYNC16(smem_u32(dst + r * 272 + c8 * 16), Bb + (size_t)r * g.ldB + c8 * 8);
        }
    };

    loadA(0, 0); loadB(0, 0);
    CP_COMMIT();

    #pragma unroll 1
    for (int s = 0; s < 4; s++) {
        int b = s & 1;
        if (s < 3) { loadA(s + 1, b ^ 1); loadB(s + 1, b ^ 1); CP_COMMIT(); }
        if (s < 3) { CP_WAIT(1); } else { CP_WAIT(0); }
        __syncthreads();

        const __half* As = (const __half*)(smc + b * A_BUF_B) + warp_m * 32 * A_PITCH_H;
        const __half* Bs = (const __half*)(smc + B_BASE_B + b * B_BUF_B);
        #pragma unroll
        for (int kk = 0; kk < 4; kk++) {
            wmma::fragment<wmma::matrix_a, 16, 16, 16, __half, wmma::row_major> af[2];
            wmma::load_matrix_sync(af[0], As + kk * 16, A_PITCH_H);
            wmma::load_matrix_sync(af[1], As + 16 * A_PITCH_H + kk * 16, A_PITCH_H);
            #pragma unroll
            for (int t = 0; t < 4; t++) {
                wmma::fragment<wmma::matrix_b, 16, 16, 16, __half, wmma::row_major> bf;
                wmma::load_matrix_sync(bf, Bs + kk * 16 * B_PITCH_H + warp_n * 64 + t * 16, B_PITCH_H);
                wmma::mma_sync(cfr[0][t], af[0], bf, cfr[0][t]);
                wmma::mma_sync(cfr[1][t], af[1], bf, cfr[1][t]);
            }
        }
        __syncthreads();
    }

    float* stg = (float*)smc;
    #pragma unroll
    for (int i = 0; i < 2; i++)
        #pragma unroll
        for (int t = 0; t < 4; t++)
            wmma::store_matrix_sync(stg + (warp_m * 32 + i * 16) * 132 + warp_n * 64 + t * 16,
                                    cfr[i][t], 132, wmma::mem_row_major);
    __syncthreads();

    #pragma unroll
    for (int id = tid; id < 128 * 32; id += 256) {
        int r = id >> 5;
        int c = (id & 31) * 4;
        if (col0 + c < g.Nout) {
            float4 v = *(const float4*)(stg + r * 132 + c);
            float4 bv = *(const float4*)(g.bias + col0 + c);
            __half2 h0 = __floats2half2_rn(v.x + bv.x, v.y + bv.y);
            __half2 h1 = __floats2half2_rn(v.z + bv.z, v.w + bv.w);
            uint2 pk = make_uint2(h2_bits(h0), h2_bits(h1));
            *(uint2*)(g.C + (size_t)(m0 + r) * g.Nout + col0 + c) = pk;
        }
    }
}

// ---------------- CSR build ----------------
__global__ void count2_kernel(const int* __restrict__ sg_dst, const int* __restrict__ gs_dst,
                              int* __restrict__ dsg, int* __restrict__ dgs) {
    int e = blockIdx.x * blockDim.x + threadIdx.x;
    if (e < NE) {
        atomicAdd(&dsg[sg_dst[e]], 1);
        atomicAdd(&dgs[gs_dst[e]], 1);
    }
}

__global__ void scan2_kernel(const int* __restrict__ dsg, int* __restrict__ off_sg, int* __restrict__ cur_sg,
                             const int* __restrict__ dgs, int* __restrict__ off_gs, int* __restrict__ cur_gs) {
    const int* deg = (blockIdx.x == 0) ? dsg : dgs;
    int* off = (blockIdx.x == 0) ? off_sg : off_gs;
    int* cur = (blockIdx.x == 0) ? cur_sg : cur_gs;
    const int n  = (blockIdx.x == 0) ? NG : NS;
    const int ch = (blockIdx.x == 0) ? 20 : 4;
    __shared__ int wsum[32];
    int tid = threadIdx.x, lane = tid & 31, wid = tid >> 5;
    int base = tid * ch;

    int vals[20];
    int tsum = 0;
    #pragma unroll 20
    for (int j = 0; j < 20; j++) {
        if (j < ch) {
            int i = base + j;
            int v = (i < n) ? deg[i] : 0;
            vals[j] = tsum;
            tsum += v;
        }
    }
    int x = tsum;
    #pragma unroll
    for (int o = 1; o < 32; o <<= 1) {
        int t = __shfl_up_sync(0xFFFFFFFFu, x, o);
        if (lane >= o) x += t;
    }
    if (lane == 31) wsum[wid] = x;
    __syncthreads();
    if (wid == 0) {
        int y = wsum[lane];
        #pragma unroll
        for (int o = 1; o < 32; o <<= 1) {
            int t = __shfl_up_sync(0xFFFFFFFFu, y, o);
            if (lane >= o) y += t;
        }
        wsum[lane] = y;
    }
    __syncthreads();
    int pre = (wid > 0) ? wsum[wid - 1] : 0;
    int tbase = pre + x - tsum;

    #pragma unroll 20
    for (int j = 0; j < 20; j++) {
        if (j < ch) {
            int i = base + j;
            if (i < n) {
                int e = tbase + vals[j];
                off[i] = e;
                cur[i] = e;
            }
        }
    }
    if (tid == 0) off[n] = wsum[31];
}

__global__ void scatter2_kernel(const int* __restrict__ sg_src, const int* __restrict__ sg_dst,
                                int* __restrict__ cur_sg, int* __restrict__ srcs_sg,
                                const int* __restrict__ gs_src, const int* __restrict__ gs_dst,
                                int* __restrict__ cur_gs, int* __restrict__ srcs_gs) {
    int e = blockIdx.x * blockDim.x + threadIdx.x;
    if (e < NE) {
        int p = atomicAdd(&cur_sg[sg_dst[e]], 1);
        srcs_sg[p] = sg_src[e];
        int q = atomicAdd(&cur_gs[gs_dst[e]], 1);
        srcs_gs[q] = gs_src[e];
    }
}

// ---------------- layer-1 GAT core: warp per dst, fp16 tables ----------------
__device__ __forceinline__ void gat1_core(int d, int lane,
                                          const int* __restrict__ off, const int* __restrict__ srcs,
                                          const __half* __restrict__ xl, const __half* __restrict__ xr,
                                          const float* __restrict__ att, const float* __restrict__ bias,
                                          const __half* __restrict__ self, __half* __restrict__ out) {
    float attv[8], xrv[8];
    {
        const float4* pa = (const float4*)(att + lane * 8);
        float4 a0 = pa[0], a1 = pa[1];
        attv[0]=a0.x; attv[1]=a0.y; attv[2]=a0.z; attv[3]=a0.w;
        attv[4]=a1.x; attv[5]=a1.y; attv[6]=a1.z; attv[7]=a1.w;
        uint4 rr = *(const uint4*)(xr + (size_t)d * HC1 + lane * 8);
        const __half2* rh = (const __half2*)&rr;
        #pragma unroll
        for (int j = 0; j < 4; j++) {
            float2 f = __half22float2(rh[j]);
            xrv[2*j] = f.x; xrv[2*j+1] = f.y;
        }
    }
    int b0 = off[d], b1 = off[d + 1];

    float m = -1e30f, den = 0.f, acc[8] = {};
    int s = (b0 < b1) ? srcs[b0] : 0;
    for (int i = b0; i < b1; i++) {
        int s_next = (i + 1 < b1) ? srcs[i + 1] : 0;
        uint4 tt = *(const uint4*)(xl + (size_t)s * HC1 + lane * 8);
        const __half2* th = (const __half2*)&tt;
        float t[8];
        #pragma unroll
        for (int j = 0; j < 4; j++) {
            float2 f = __half22float2(th[j]);
            t[2*j] = f.x; t[2*j+1] = f.y;
        }
        float pp = 0.f;
        #pragma unroll
        for (int v = 0; v < 8; v++) {
            float g = t[v] + xrv[v];
            g = g > 0.f ? g : 0.2f * g;
            pp = fmaf(g, attv[v], pp);
        }
        pp += __shfl_xor_sync(0xFFFFFFFFu, pp, 1);
        pp += __shfl_xor_sync(0xFFFFFFFFu, pp, 2);
        pp += __shfl_xor_sync(0xFFFFFFFFu, pp, 4);
        float mn = fmaxf(m, pp);
        float sc = __expf(m - mn);
        float a  = __expf(pp - mn);
        den = den * sc + a;
        #pragma unroll
        for (int v = 0; v < 8; v++) acc[v] = fmaf(acc[v], sc, a * t[v]);
        m = mn;
        s = s_next;
    }

    float sv[8] = {};
    if (self) {
        uint4 ss = *(const uint4*)(self + (size_t)d * C1 + (lane & 7) * 8);
        const __half2* sh = (const __half2*)&ss;
        #pragma unroll
        for (int j = 0; j < 4; j++) {
            float2 f = __half22float2(sh[j]);
            sv[2*j] = f.x; sv[2*j+1] = f.y;
        }
    }

    float inv = 1.f / (den + 1e-16f);
    __half2 hv[4];
    #pragma unroll
    for (int j = 0; j < 4; j++) {
        float x0 = acc[2*j]   * inv + bias[lane * 8 + 2*j]   + sv[2*j];
        float x1 = acc[2*j+1] * inv + bias[lane * 8 + 2*j+1] + sv[2*j+1];
        x0 = x0 > 0.f ? x0 : (__expf(x0) - 1.f);
        x1 = x1 > 0.f ? x1 : (__expf(x1) - 1.f);
        hv[j] = __floats2half2_rn(x0, x1);
    }
    *(uint4*)(out + (size_t)d * HC1 + lane * 8) = *(uint4*)hv;
}

__global__ void gat1_dual(const int* __restrict__ off_sg, const int* __restrict__ srcs_sg,
                          const __half* __restrict__ xl_sg, const __half* __restrict__ xr_sg,
                          const float* __restrict__ att_sg, const float* __restrict__ bias_sg,
                          __half* __restrict__ out_sg,
                          const int* __restrict__ off_gs, const int* __restrict__ srcs_gs,
                          const __half* __restrict__ xl_gs, const __half* __restrict__ xr_gs,
                          const float* __restrict__ att_gs, const float* __restrict__ bias_gs,
                          const __half* __restrict__ self_gs, __half* __restrict__ out_gs) {
    int w = (blockIdx.x * blockDim.x + threadIdx.x) >> 5;
    int lane = threadIdx.x & 31;
    if (w < NG) {
        gat1_core(w, lane, off_sg, srcs_sg, xl_sg, xr_sg, att_sg, bias_sg, nullptr, out_sg);
    } else if (w < NG + NS) {
        gat1_core(w - NG, lane, off_gs, srcs_gs, xl_gs, xr_gs, att_gs, bias_gs, self_gs, out_gs);
    }
}

// ---------------- layer-3 GAT: warp per dst, fp16 tables, head mean ----------------
__global__ void gat3_warp(const int* __restrict__ off, const int* __restrict__ srcs,
                          const __half* __restrict__ xl, const __half* __restrict__ xr,
                          const float* __restrict__ att, const float* __restrict__ bias3,
                          const __half* __restrict__ sl3, float* __restrict__ out) {
    int d = (blockIdx.x * blockDim.x + threadIdx.x) >> 5;
    int lane = threadIdx.x & 31;
    if (d >= NS) return;

    float attv[16], xrv[16];
    {
        const float4* pa = (const float4*)(att + lane * 16);
        #pragma unroll
        for (int q = 0; q < 4; q++) {
            float4 a = pa[q];
            attv[q*4+0]=a.x; attv[q*4+1]=a.y; attv[q*4+2]=a.z; attv[q*4+3]=a.w;
        }
        uint4 r0 = *(const uint4*)(xr + (size_t)d * HC3 + lane * 16);
        uint4 r1 = *(const uint4*)(xr + (size_t)d * HC3 + lane * 16 + 8);
        const __half2* rh0 = (const __half2*)&r0;
        const __half2* rh1 = (const __half2*)&r1;
        #pragma unroll
        for (int j = 0; j < 4; j++) {
            float2 f0 = __half22float2(rh0[j]);
            float2 f1 = __half22float2(rh1[j]);
            xrv[2*j] = f0.x; xrv[2*j+1] = f0.y;
            xrv[8+2*j] = f1.x; xrv[8+2*j+1] = f1.y;
        }
    }
    int b0 = off[d], b1 = off[d + 1];

    float m = -1e30f, den = 0.f, acc[16] = {};
    int s = (b0 < b1) ? srcs[b0] : 0;
    for (int i = b0; i < b1; i++) {
        int s_next = (i + 1 < b1) ? srcs[i + 1] : 0;
        uint4 t0 = *(const uint4*)(xl + (size_t)s * HC3 + lane * 16);
        uint4 t1 = *(const uint4*)(xl + (size_t)s * HC3 + lane * 16 + 8);
        const __half2* th0 = (const __half2*)&t0;
        const __half2* th1 = (const __half2*)&t1;
        float t[16];
        #pragma unroll
        for (int j = 0; j < 4; j++) {
            float2 f0 = __half22float2(th0[j]);
            float2 f1 = __half22float2(th1[j]);
            t[2*j] = f0.x; t[2*j+1] = f0.y;
            t[8+2*j] = f1.x; t[8+2*j+1] = f1.y;
        }
        float pp = 0.f;
        #pragma unroll
        for (int v = 0; v < 16; v++) {
            float g = t[v] + xrv[v];
            g = g > 0.f ? g : 0.2f * g;
            pp = fmaf(g, attv[v], pp);
        }
        pp += __shfl_xor_sync(0xFFFFFFFFu, pp, 1);
        pp += __shfl_xor_sync(0xFFFFFFFFu, pp, 2);
        pp += __shfl_xor_sync(0xFFFFFFFFu, pp, 4);
        float mn = fmaxf(m, pp);
        float sc = __expf(m - mn);
        float a  = __expf(pp - mn);
        den = den * sc + a;
        #pragma unroll
        for (int v = 0; v < 16; v++) acc[v] = fmaf(acc[v], sc, a * t[v]);
        m = mn;
        s = s_next;
    }

    float inv = 1.f / (den + 1e-16f);
    float ov[16];
    #pragma unroll
    for (int v = 0; v < 16; v++) {
        float hv = acc[v] * inv;
        hv += __shfl_xor_sync(0xFFFFFFFFu, hv, 8);
        hv += __shfl_xor_sync(0xFFFFFFFFu, hv, 16);
        ov[v] = 0.25f * hv;
    }
    if (lane < 8) {
        uint4 s0 = *(const uint4*)(sl3 + (size_t)d * C3 + lane * 16);
        uint4 s1 = *(const uint4*)(sl3 + (size_t)d * C3 + lane * 16 + 8);
        const __half2* sh0 = (const __half2*)&s0;
        const __half2* sh1 = (const __half2*)&s1;
        float sv[16];
        #pragma unroll
        for (int j = 0; j < 4; j++) {
            float2 f0 = __half22float2(sh0[j]);
            float2 f1 = __half22float2(sh1[j]);
            sv[2*j] = f0.x; sv[2*j+1] = f0.y;
            sv[8+2*j] = f1.x; sv[8+2*j+1] = f1.y;
        }
        #pragma unroll
        for (int v = 0; v < 16; v++) {
            int c = lane * 16 + v;
            float x = ov[v] + bias3[c] + sv[v];
            ov[v] = x > 0.f ? x : (__expf(x) - 1.f);
        }
        float4* po = (float4*)(out + (size_t)d * C3 + lane * 16);
        #pragma unroll
        for (int q = 0; q < 4; q++)
            po[q] = make_float4(ov[q*4+0], ov[q*4+1], ov[q*4+2], ov[q*4+3]);
    }
}

// ---------------- host launch ----------------
static inline __half* symh(const void* s) {
    void* p = nullptr;
    cudaGetSymbolAddress(&p, s);
    return (__half*)p;
}
static inline float* symf(const void* s) {
    void* p = nullptr;
    cudaGetSymbolAddress(&p, s);
    return (float*)p;
}
static inline int* symi(const void* s) {
    void* p = nullptr;
    cudaGetSymbolAddress(&p, s);
    return (int*)p;
}

extern "C" void kernel_launch(void* const* d_in, const int* in_sizes, int n_in,
                              void* d_out, int out_size) {
    const float* x_sample = (const float*)d_in[0];
    const float* x_gene   = (const float*)d_in[1];
    const int*   sg_src   = (const int*)d_in[2];
    const int*   sg_dst   = (const int*)d_in[3];
    const int*   gs_src   = (const int*)d_in[4];
    const int*   gs_dst   = (const int*)d_in[5];
    const float* Wl1_sg = (const float*)d_in[6];
    const float* bl1_sg = (const float*)d_in[7];
    const float* Wr1_sg = (const float*)d_in[8];
    const float* br1_sg = (const float*)d_in[9];
    const float* att1_sg  = (const float*)d_in[10];
    const float* bias1_sg = (const float*)d_in[11];
    const float* Wl1_gs = (const float*)d_in[12];
    const float* bl1_gs = (const float*)d_in[13];
    const float* Wr1_gs = (const float*)d_in[14];
    const float* br1_gs = (const float*)d_in[15];
    const float* att1_gs  = (const float*)d_in[16];
    const float* bias1_gs = (const float*)d_in[17];
    const float* Wl3_gs = (const float*)d_in[18];
    const float* bl3_gs = (const float*)d_in[19];
    const float* Wr3_gs = (const float*)d_in[20];
    const float* br3_gs = (const float*)d_in[21];
    const float* att3_gs  = (const float*)d_in[22];
    const float* bias3_gs = (const float*)d_in[23];
    const float* sl1_W = (const float*)d_in[24];
    const float* sl1_b = (const float*)d_in[25];
    const float* sl3_W = (const float*)d_in[26];
    const float* sl3_b = (const float*)d_in[27];
    float* out = (float*)d_out;

    __half* xl_sg = symh(g_xl_sg);
    __half* xr_sg = symh(g_xr_sg);
    __half* xl_gs = symh(g_xl_gs);
    __half* xr_gs = symh(g_xr_gs);
    __half* sl1 = symh(g_sl1);
    __half* xl3 = symh(g_xl3);
    __half* xr3 = symh(g_xr3);
    __half* sl3 = symh(g_sl3);
    float* b5p = symf(g_b5p);
    __half* hxs = symh(g_hxs);
    __half* hxg = symh(g_hxg);
    __half* hWl1sg = symh(g_hWl1sg);
    __half* hWr1sg = symh(g_hWr1sg);
    __half* hWl1gs = symh(g_hWl1gs);
    __half* hWr1gs = symh(g_hWr1gs);
    __half* hw5 = symh(g_hw5);
    __half* hWl3 = symh(g_hWl3);
    __half* hWr3 = symh(g_hWr3);
    __half* hsl3W = symh(g_hsl3W);
    __half* x1h_gene = symh(g_x1h_gene);
    __half* x1h_sample = symh(g_x1h_sample);
    int* deg_sg = symi(g_deg_sg);
    int* deg_gs = symi(g_deg_gs);
    int* off_sg = symi(g_off_sg);
    int* cur_sg = symi(g_cur_sg);
    int* srcs_sg = symi(g_srcs_sg);
    int* off_gs = symi(g_off_gs);
    int* cur_gs = symi(g_cur_gs);
    int* srcs_gs = symi(g_srcs_gs);

    cudaFuncSetAttribute(gemm_batch, cudaFuncAttributeMaxDynamicSharedMemorySize, GEMM_SMEM);

    dim3 tb(256);
    int eb = (NE + 255) / 256;

    // ----- fork: CSR chain on side stream -----
    cudaStream_t sB;
    cudaStreamCreateWithFlags(&sB, cudaStreamNonBlocking);
    cudaEvent_t evFork, evJoin;
    cudaEventCreateWithFlags(&evFork, cudaEventDisableTiming);
    cudaEventCreateWithFlags(&evJoin, cudaEventDisableTiming);

    cudaEventRecord(evFork, 0);
    cudaStreamWaitEvent(sB, evFork, 0);

    cudaMemsetAsync(deg_sg, 0, NG * sizeof(int), sB);
    cudaMemsetAsync(deg_gs, 0, NS * sizeof(int), sB);
    count2_kernel<<<eb, tb, 0, sB>>>(sg_dst, gs_dst, deg_sg, deg_gs);
    scan2_kernel<<<2, 1024, 0, sB>>>(deg_sg, off_sg, cur_sg, deg_gs, off_gs, cur_gs);
    scatter2_kernel<<<eb, tb, 0, sB>>>(sg_src, sg_dst, cur_sg, srcs_sg,
                                       gs_src, gs_dst, cur_gs, srcs_gs);
    cudaEventRecord(evJoin, sB);

    // main stream: conversion + layer-1 GEMMs
    cvt_all<<<(NG * DIN / 2 + 255) / 256, tb>>>(
        x_sample, x_gene, Wl1_sg, Wr1_sg, Wl1_gs, Wr1_gs, sl1_W, sl1_b,
        Wl3_gs, Wr3_gs, sl3_W,
        hxs, hxg, hWl1sg, hWr1sg, hWl1gs, hWr1gs, hw5, b5p, hWl3, hWr3, hsl3W);

    const int MB_NS = NS / 128;            // 32
    const int MB_NG = (NG + 127) / 128;    // 157

    {
        GemmBatch P;
        int blk = 0;
        P.seg[0] = {hxs, hWl1sg, bl1_sg, xl_sg, HC1, NS, HC1, 2, blk}; blk += 2 * MB_NS;
        P.seg[1] = {hxg, hWr1sg, br1_sg, xr_sg, HC1, NG, HC1, 2, blk}; blk += 2 * MB_NG;
        P.seg[2] = {hxg, hWl1gs, bl1_gs, xl_gs, HC1, NG, HC1, 2, blk}; blk += 2 * MB_NG;
        P.seg[3] = {hxs, hWr1gs, br1_gs, xr_gs, HC1, NS, HC1, 2, blk}; blk += 2 * MB_NS;
        P.seg[4] = {hxs, hw5,    b5p,    sl1,   128, NS, C1,  1, blk}; blk += MB_NS;
        P.seg[5] = P.seg[4];
        P.nseg = 5;
        gemm_batch<<<blk, GEMM_THREADS, GEMM_SMEM>>>(P);
    }

    cudaStreamWaitEvent(0, evJoin, 0);

    gat1_dual<<<((NG + NS) * 32 + 255) / 256, tb>>>(
        off_sg, srcs_sg, xl_sg, xr_sg, att1_sg, bias1_sg, x1h_gene,
        off_gs, srcs_gs, xl_gs, xr_gs, att1_gs, bias1_gs, sl1, x1h_sample);

    {
        GemmBatch P;
        int blk = 0;
        P.seg[0] = {x1h_gene,   hWl3,  bl3_gs, xl3, HC3, NG, HC3, 4, blk}; blk += 4 * MB_NG;
        P.seg[1] = {x1h_sample, hWr3,  br3_gs, xr3, HC3, NS, HC3, 4, blk}; blk += 4 * MB_NS;
        P.seg[2] = {x1h_sample, hsl3W, sl3_b,  sl3, C3,  NS, C3,  1, blk}; blk += MB_NS;
        P.seg[3] = P.seg[2];
        P.seg[4] = P.seg[2];
        P.seg[5] = P.seg[2];
        P.nseg = 3;
        gemm_batch<<<blk, GEMM_THREADS, GEMM_SMEM>>>(P);
    }

    gat3_warp<<<(NS * 32 + 255) / 256, tb>>>(off_gs, srcs_gs, xl3, xr3, att3_gs, bias3_gs, sl3, out);
}

// round 16
// speedup vs baseline: 1.1774x; 1.0363x over previous
#include <cuda_runtime.h>
#include <cuda_fp16.h>
#include <mma.h>
#include <math.h>
#include <stddef.h>
#include <stdint.h>

using namespace nvcuda;

// ---------------- problem constants ----------------
#define NS   4096
#define NG   20000
#define NGP  20096
#define NE   131072
#define DIN  256
#define H    4
#define C1   64
#define C3   128
#define HC1  256
#define HC3  512

// ---------------- device scratch (all GEMM outputs fp16) ----------------
__device__ __align__(128) __half g_xl_sg[NS * HC1];
__device__ __align__(128) __half g_xr_sg[NGP * HC1];
__device__ __align__(128) __half g_xl_gs[NGP * HC1];
__device__ __align__(128) __half g_xr_gs[NS * HC1];
__device__ __align__(128) __half g_sl1[NS * C1];
__device__ __align__(128) __half g_xl3[NGP * HC3];
__device__ __align__(128) __half g_xr3[NS * HC3];
__device__ __align__(128) __half g_sl3[NS * C3];
__device__ __align__(128) float  g_b5p[128];

__device__ __align__(128) __half g_hxs[NS * DIN];
__device__ __align__(128) __half g_hxg[NG * DIN];
__device__ __align__(128) __half g_hWl1sg[DIN * HC1];
__device__ __align__(128) __half g_hWr1sg[DIN * HC1];
__device__ __align__(128) __half g_hWl1gs[DIN * HC1];
__device__ __align__(128) __half g_hWr1gs[DIN * HC1];
__device__ __align__(128) __half g_hw5[DIN * 128];
__device__ __align__(128) __half g_hWl3[DIN * HC3];
__device__ __align__(128) __half g_hWr3[DIN * HC3];
__device__ __align__(128) __half g_hsl3W[DIN * C3];
__device__ __align__(128) __half g_x1h_gene[NG * HC1];
__device__ __align__(128) __half g_x1h_sample[NS * HC1];

__device__ int g_deg_sg[NG];
__device__ int g_deg_gs[NS];
__device__ int g_off_sg[NG + 1];
__device__ int g_cur_sg[NG];
__device__ int g_srcs_sg[NE];
__device__ int g_off_gs[NS + 1];
__device__ int g_cur_gs[NS];
__device__ int g_srcs_gs[NE];

// ---------------- helpers ----------------
__device__ __forceinline__ uint32_t smem_u32(const void* p) {
    uint32_t a;
    asm("{ .reg .u64 t; cvta.to.shared.u64 t, %1; cvt.u32.u64 %0, t; }" : "=r"(a) : "l"(p));
    return a;
}
__device__ __forceinline__ uint32_t h2_bits(__half2 h) {
    uint32_t u;
    memcpy(&u, &h, 4);
    return u;
}
__device__ __forceinline__ uint2 f4_to_h4(float4 v) {
    __half2 h0 = __floats2half2_rn(v.x, v.y);
    __half2 h1 = __floats2half2_rn(v.z, v.w);
    return make_uint2(h2_bits(h0), h2_bits(h1));
}
#define CP_ASYNC16(dst, src) \
    asm volatile("cp.async.ca.shared.global [%0], [%1], 16;" :: "r"(dst), "l"(src))
#define CP_COMMIT() asm volatile("cp.async.commit_group;")
#define CP_WAIT(n)  asm volatile("cp.async.wait_group %0;" :: "n"(n))

// ---------------- fp32 -> fp16 conversion (float4 vectorized) ----------------
__global__ void cvt_all(const float* __restrict__ xs, const float* __restrict__ xg,
                        const float* __restrict__ Wl1sg, const float* __restrict__ Wr1sg,
                        const float* __restrict__ Wl1gs, const float* __restrict__ Wr1gs,
                        const float* __restrict__ w5, const float* __restrict__ b5,
                        const float* __restrict__ Wl3, const float* __restrict__ Wr3,
                        const float* __restrict__ sl3W,
                        __half* __restrict__ hxs, __half* __restrict__ hxg,
                        __half* __restrict__ hWl1sg, __half* __restrict__ hWr1sg,
                        __half* __restrict__ hWl1gs, __half* __restrict__ hWr1gs,
                        __half* __restrict__ hw5, float* __restrict__ b5p,
                        __half* __restrict__ hWl3, __half* __restrict__ hWr3,
                        __half* __restrict__ hsl3W) {
    int i = blockIdx.x * blockDim.x + threadIdx.x;   // quad index
    if (i < NS * DIN / 4)
        ((uint2*)hxs)[i] = f4_to_h4(((const float4*)xs)[i]);
    if (i < NG * DIN / 4)
        ((uint2*)hxg)[i] = f4_to_h4(((const float4*)xg)[i]);
    if (i < DIN * HC1 / 4) {
        ((uint2*)hWl1sg)[i] = f4_to_h4(((const float4*)Wl1sg)[i]);
        ((uint2*)hWr1sg)[i] = f4_to_h4(((const float4*)Wr1sg)[i]);
        ((uint2*)hWl1gs)[i] = f4_to_h4(((const float4*)Wl1gs)[i]);
        ((uint2*)hWr1gs)[i] = f4_to_h4(((const float4*)Wr1gs)[i]);
    }
    if (i < DIN * 128 / 4) {
        int k = i >> 5, c = (i & 31) * 4;            // 32 quads per 128-col row
        uint2 hv;
        if (c < C1) {
            hv = f4_to_h4(*(const float4*)(w5 + k * C1 + c));
        } else {
            hv = make_uint2(0, 0);
        }
        ((uint2*)hw5)[i] = hv;
        ((uint2*)hsl3W)[i] = f4_to_h4(((const float4*)sl3W)[i]);
    }
    if (i < 128) b5p[i] = (i < C1) ? b5[i] : 0.f;
    if (i < DIN * HC3 / 4) {
        ((uint2*)hWl3)[i] = f4_to_h4(((const float4*)Wl3)[i]);
        ((uint2*)hWr3)[i] = f4_to_h4(((const float4*)Wr3)[i]);
    }
}

// ---------------- batched fp16 WMMA GEMM (fp32 accum, fp16 output) ----------------
struct GemmSeg {
    const __half* A; const __half* B; const float* bias; __half* C;
    int ldB; int M; int Nout; int nx; int blk0;
};
struct GemmBatch { GemmSeg seg[6]; int nseg; };

#define GEMM_THREADS 256
#define A_PITCH_H 72
#define B_PITCH_H 136
#define A_BUF_B   18432
#define B_BUF_B   17408
#define B_BASE_B  36864
#define GEMM_SMEM 71680

__global__ void __launch_bounds__(GEMM_THREADS) gemm_batch(GemmBatch P) {
    extern __shared__ char smc[];
    const int tid = threadIdx.x;
    const int wid = tid >> 5;
    const int warp_m = wid >> 1;
    const int warp_n = wid & 1;

    GemmSeg g = P.seg[0];
    #pragma unroll
    for (int i = 1; i < 6; i++)
        if (i < P.nseg && (int)blockIdx.x >= P.seg[i].blk0) g = P.seg[i];
    int lb = blockIdx.x - g.blk0;
    const int m0 = (lb / g.nx) * 128;
    const int col0 = (lb % g.nx) * 128;

    wmma::fragment<wmma::accumulator, 16, 16, 16, float> cfr[2][4];
    #pragma unroll
    for (int i = 0; i < 2; i++)
        #pragma unroll
        for (int t = 0; t < 4; t++) wmma::fill_fragment(cfr[i][t], 0.f);

    auto loadA = [&](int s, int b) {
        const __half* Ab = g.A + (size_t)m0 * 256 + s * 64;
        char* dst = smc + b * A_BUF_B;
        #pragma unroll
        for (int i = 0; i < 4; i++) {
            int ch = tid + i * 256;
            int r = ch >> 3, c8 = ch & 7;
            char* dp = dst + r * 144 + c8 * 16;
            if (m0 + r < g.M) {
                CP_ASYNC16(smem_u32(dp), Ab + (size_t)r * 256 + c8 * 8);
            } else {
                *(uint4*)dp = make_uint4(0, 0, 0, 0);
            }
        }
    };
    auto loadB = [&](int s, int b) {
        const __half* Bb = g.B + (size_t)(s * 64) * g.ldB + col0;
        char* dst = smc + B_BASE_B + b * B_BUF_B;
        #pragma unroll
        for (int i = 0; i < 4; i++) {
            int ch = tid + i * 256;
            int r = ch >> 4, c8 = ch & 15;
            CP_ASYNC16(smem_u32(dst + r * 272 + c8 * 16), Bb + (size_t)r * g.ldB + c8 * 8);
        }
    };

    loadA(0, 0); loadB(0, 0);
    CP_COMMIT();

    #pragma unroll 1
    for (int s = 0; s < 4; s++) {
        int b = s & 1;
        if (s < 3) { loadA(s + 1, b ^ 1); loadB(s + 1, b ^ 1); CP_COMMIT(); }
        if (s < 3) { CP_WAIT(1); } else { CP_WAIT(0); }
        __syncthreads();

        const __half* As = (const __half*)(smc + b * A_BUF_B) + warp_m * 32 * A_PITCH_H;
        const __half* Bs = (const __half*)(smc + B_BASE_B + b * B_BUF_B);
        #pragma unroll
        for (int kk = 0; kk < 4; kk++) {
            wmma::fragment<wmma::matrix_a, 16, 16, 16, __half, wmma::row_major> af[2];
            wmma::load_matrix_sync(af[0], As + kk * 16, A_PITCH_H);
            wmma::load_matrix_sync(af[1], As + 16 * A_PITCH_H + kk * 16, A_PITCH_H);
            #pragma unroll
            for (int t = 0; t < 4; t++) {
                wmma::fragment<wmma::matrix_b, 16, 16, 16, __half, wmma::row_major> bf;
                wmma::load_matrix_sync(bf, Bs + kk * 16 * B_PITCH_H + warp_n * 64 + t * 16, B_PITCH_H);
                wmma::mma_sync(cfr[0][t], af[0], bf, cfr[0][t]);
                wmma::mma_sync(cfr[1][t], af[1], bf, cfr[1][t]);
            }
        }
        __syncthreads();
    }

    float* stg = (float*)smc;
    #pragma unroll
    for (int i = 0; i < 2; i++)
        #pragma unroll
        for (int t = 0; t < 4; t++)
            wmma::store_matrix_sync(stg + (warp_m * 32 + i * 16) * 132 + warp_n * 64 + t * 16,
                                    cfr[i][t], 132, wmma::mem_row_major);
    __syncthreads();

    #pragma unroll
    for (int id = tid; id < 128 * 32; id += 256) {
        int r = id >> 5;
        int c = (id & 31) * 4;
        if (col0 + c < g.Nout) {
            float4 v = *(const float4*)(stg + r * 132 + c);
            float4 bv = *(const float4*)(g.bias + col0 + c);
            __half2 h0 = __floats2half2_rn(v.x + bv.x, v.y + bv.y);
            __half2 h1 = __floats2half2_rn(v.z + bv.z, v.w + bv.w);
            uint2 pk = make_uint2(h2_bits(h0), h2_bits(h1));
            *(uint2*)(g.C + (size_t)(m0 + r) * g.Nout + col0 + c) = pk;
        }
    }
}

// ---------------- CSR build ----------------
__global__ void count2_kernel(const int* __restrict__ sg_dst, const int* __restrict__ gs_dst,
                              int* __restrict__ dsg, int* __restrict__ dgs) {
    int e = blockIdx.x * blockDim.x + threadIdx.x;
    if (e < NE) {
        atomicAdd(&dsg[sg_dst[e]], 1);
        atomicAdd(&dgs[gs_dst[e]], 1);
    }
}

__global__ void scan2_kernel(const int* __restrict__ dsg, int* __restrict__ off_sg, int* __restrict__ cur_sg,
                             const int* __restrict__ dgs, int* __restrict__ off_gs, int* __restrict__ cur_gs) {
    const int* deg = (blockIdx.x == 0) ? dsg : dgs;
    int* off = (blockIdx.x == 0) ? off_sg : off_gs;
    int* cur = (blockIdx.x == 0) ? cur_sg : cur_gs;
    const int n  = (blockIdx.x == 0) ? NG : NS;
    const int ch = (blockIdx.x == 0) ? 20 : 4;
    __shared__ int wsum[32];
    int tid = threadIdx.x, lane = tid & 31, wid = tid >> 5;
    int base = tid * ch;

    int vals[20];
    int tsum = 0;
    #pragma unroll 20
    for (int j = 0; j < 20; j++) {
        if (j < ch) {
            int i = base + j;
            int v = (i < n) ? deg[i] : 0;
            vals[j] = tsum;
            tsum += v;
        }
    }
    int x = tsum;
    #pragma unroll
    for (int o = 1; o < 32; o <<= 1) {
        int t = __shfl_up_sync(0xFFFFFFFFu, x, o);
        if (lane >= o) x += t;
    }
    if (lane == 31) wsum[wid] = x;
    __syncthreads();
    if (wid == 0) {
        int y = wsum[lane];
        #pragma unroll
        for (int o = 1; o < 32; o <<= 1) {
            int t = __shfl_up_sync(0xFFFFFFFFu, y, o);
            if (lane >= o) y += t;
        }
        wsum[lane] = y;
    }
    __syncthreads();
    int pre = (wid > 0) ? wsum[wid - 1] : 0;
    int tbase = pre + x - tsum;

    #pragma unroll 20
    for (int j = 0; j < 20; j++) {
        if (j < ch) {
            int i = base + j;
            if (i < n) {
                int e = tbase + vals[j];
                off[i] = e;
                cur[i] = e;
            }
        }
    }
    if (tid == 0) off[n] = wsum[31];
}

__global__ void scatter2_kernel(const int* __restrict__ sg_src, const int* __restrict__ sg_dst,
                                int* __restrict__ cur_sg, int* __restrict__ srcs_sg,
                                const int* __restrict__ gs_src, const int* __restrict__ gs_dst,
                                int* __restrict__ cur_gs, int* __restrict__ srcs_gs) {
    int e = blockIdx.x * blockDim.x + threadIdx.x;
    if (e < NE) {
        int p = atomicAdd(&cur_sg[sg_dst[e]], 1);
        srcs_sg[p] = sg_src[e];
        int q = atomicAdd(&cur_gs[gs_dst[e]], 1);
        srcs_gs[q] = gs_src[e];
    }
}

// ---------------- layer-1 GAT core: warp per dst, fp16 tables, prefetched gather ----------------
__device__ __forceinline__ void gat1_core(int d, int lane,
                                          const int* __restrict__ off, const int* __restrict__ srcs,
                                          const __half* __restrict__ xl, const __half* __restrict__ xr,
                                          const float* __restrict__ att, const float* __restrict__ bias,
                                          const __half* __restrict__ self, __half* __restrict__ out) {
    float attv[8], xrv[8];
    {
        const float4* pa = (const float4*)(att + lane * 8);
        float4 a0 = pa[0], a1 = pa[1];
        attv[0]=a0.x; attv[1]=a0.y; attv[2]=a0.z; attv[3]=a0.w;
        attv[4]=a1.x; attv[5]=a1.y; attv[6]=a1.z; attv[7]=a1.w;
        uint4 rr = *(const uint4*)(xr + (size_t)d * HC1 + lane * 8);
        const __half2* rh = (const __half2*)&rr;
        #pragma unroll
        for (int j = 0; j < 4; j++) {
            float2 f = __half22float2(rh[j]);
            xrv[2*j] = f.x; xrv[2*j+1] = f.y;
        }
    }
    int b0 = off[d], b1 = off[d + 1];

    float m = -1e30f, den = 0.f, acc[8] = {};
    uint4 tt = make_uint4(0, 0, 0, 0);
    if (b0 < b1) {
        int s0 = srcs[b0];
        tt = *(const uint4*)(xl + (size_t)s0 * HC1 + lane * 8);
    }
    for (int i = b0; i < b1; i++) {
        // prefetch next row before the dependent compute chain
        uint4 tn = make_uint4(0, 0, 0, 0);
        if (i + 1 < b1) {
            int sn = srcs[i + 1];
            tn = *(const uint4*)(xl + (size_t)sn * HC1 + lane * 8);
        }
        const __half2* th = (const __half2*)&tt;
        float t[8];
        #pragma unroll
        for (int j = 0; j < 4; j++) {
            float2 f = __half22float2(th[j]);
            t[2*j] = f.x; t[2*j+1] = f.y;
        }
        float pp = 0.f;
        #pragma unroll
        for (int v = 0; v < 8; v++) {
            float g = t[v] + xrv[v];
            g = g > 0.f ? g : 0.2f * g;
            pp = fmaf(g, attv[v], pp);
        }
        pp += __shfl_xor_sync(0xFFFFFFFFu, pp, 1);
        pp += __shfl_xor_sync(0xFFFFFFFFu, pp, 2);
        pp += __shfl_xor_sync(0xFFFFFFFFu, pp, 4);
        float mn = fmaxf(m, pp);
        float sc = __expf(m - mn);
        float a  = __expf(pp - mn);
        den = den * sc + a;
        #pragma unroll
        for (int v = 0; v < 8; v++) acc[v] = fmaf(acc[v], sc, a * t[v]);
        m = mn;
        tt = tn;
    }

    float sv[8] = {};
    if (self) {
        uint4 ss = *(const uint4*)(self + (size_t)d * C1 + (lane & 7) * 8);
        const __half2* sh = (const __half2*)&ss;
        #pragma unroll
        for (int j = 0; j < 4; j++) {
            float2 f = __half22float2(sh[j]);
            sv[2*j] = f.x; sv[2*j+1] = f.y;
        }
    }

    float inv = 1.f / (den + 1e-16f);
    __half2 hv[4];
    #pragma unroll
    for (int j = 0; j < 4; j++) {
        float x0 = acc[2*j]   * inv + bias[lane * 8 + 2*j]   + sv[2*j];
        float x1 = acc[2*j+1] * inv + bias[lane * 8 + 2*j+1] + sv[2*j+1];
        x0 = x0 > 0.f ? x0 : (__expf(x0) - 1.f);
        x1 = x1 > 0.f ? x1 : (__expf(x1) - 1.f);
        hv[j] = __floats2half2_rn(x0, x1);
    }
    *(uint4*)(out + (size_t)d * HC1 + lane * 8) = *(uint4*)hv;
}

__global__ void gat1_dual(const int* __restrict__ off_sg, const int* __restrict__ srcs_sg,
                          const __half* __restrict__ xl_sg, const __half* __restrict__ xr_sg,
                          const float* __restrict__ att_sg, const float* __restrict__ bias_sg,
                          __half* __restrict__ out_sg,
                          const int* __restrict__ off_gs, const int* __restrict__ srcs_gs,
                          const __half* __restrict__ xl_gs, const __half* __restrict__ xr_gs,
                          const float* __restrict__ att_gs, const float* __restrict__ bias_gs,
                          const __half* __restrict__ self_gs, __half* __restrict__ out_gs) {
    int w = (blockIdx.x * blockDim.x + threadIdx.x) >> 5;
    int lane = threadIdx.x & 31;
    if (w < NG) {
        gat1_core(w, lane, off_sg, srcs_sg, xl_sg, xr_sg, att_sg, bias_sg, nullptr, out_sg);
    } else if (w < NG + NS) {
        gat1_core(w - NG, lane, off_gs, srcs_gs, xl_gs, xr_gs, att_gs, bias_gs, self_gs, out_gs);
    }
}

// ---------------- layer-3 GAT: warp per dst, fp16 tables, prefetch, head mean ----------------
__global__ void gat3_warp(const int* __restrict__ off, const int* __restrict__ srcs,
                          const __half* __restrict__ xl, const __half* __restrict__ xr,
                          const float* __restrict__ att, const float* __restrict__ bias3,
                          const __half* __restrict__ sl3, float* __restrict__ out) {
    int d = (blockIdx.x * blockDim.x + threadIdx.x) >> 5;
    int lane = threadIdx.x & 31;
    if (d >= NS) return;

    float attv[16], xrv[16];
    {
        const float4* pa = (const float4*)(att + lane * 16);
        #pragma unroll
        for (int q = 0; q < 4; q++) {
            float4 a = pa[q];
            attv[q*4+0]=a.x; attv[q*4+1]=a.y; attv[q*4+2]=a.z; attv[q*4+3]=a.w;
        }
        uint4 r0 = *(const uint4*)(xr + (size_t)d * HC3 + lane * 16);
        uint4 r1 = *(const uint4*)(xr + (size_t)d * HC3 + lane * 16 + 8);
        const __half2* rh0 = (const __half2*)&r0;
        const __half2* rh1 = (const __half2*)&r1;
        #pragma unroll
        for (int j = 0; j < 4; j++) {
            float2 f0 = __half22float2(rh0[j]);
            float2 f1 = __half22float2(rh1[j]);
            xrv[2*j] = f0.x; xrv[2*j+1] = f0.y;
            xrv[8+2*j] = f1.x; xrv[8+2*j+1] = f1.y;
        }
    }
    int b0 = off[d], b1 = off[d + 1];

    float m = -1e30f, den = 0.f, acc[16] = {};
    uint4 t0 = make_uint4(0, 0, 0, 0), t1 = make_uint4(0, 0, 0, 0);
    if (b0 < b1) {
        int s0 = srcs[b0];
        t0 = *(const uint4*)(xl + (size_t)s0 * HC3 + lane * 16);
        t1 = *(const uint4*)(xl + (size_t)s0 * HC3 + lane * 16 + 8);
    }
    for (int i = b0; i < b1; i++) {
        uint4 n0 = make_uint4(0, 0, 0, 0), n1 = make_uint4(0, 0, 0, 0);
        if (i + 1 < b1) {
            int sn = srcs[i + 1];
            n0 = *(const uint4*)(xl + (size_t)sn * HC3 + lane * 16);
            n1 = *(const uint4*)(xl + (size_t)sn * HC3 + lane * 16 + 8);
        }
        const __half2* th0 = (const __half2*)&t0;
        const __half2* th1 = (const __half2*)&t1;
        float t[16];
        #pragma unroll
        for (int j = 0; j < 4; j++) {
            float2 f0 = __half22float2(th0[j]);
            float2 f1 = __half22float2(th1[j]);
            t[2*j] = f0.x; t[2*j+1] = f0.y;
            t[8+2*j] = f1.x; t[8+2*j+1] = f1.y;
        }
        float pp = 0.f;
        #pragma unroll
        for (int v = 0; v < 16; v++) {
            float g = t[v] + xrv[v];
            g = g > 0.f ? g : 0.2f * g;
            pp = fmaf(g, attv[v], pp);
        }
        pp += __shfl_xor_sync(0xFFFFFFFFu, pp, 1);
        pp += __shfl_xor_sync(0xFFFFFFFFu, pp, 2);
        pp += __shfl_xor_sync(0xFFFFFFFFu, pp, 4);
        float mn = fmaxf(m, pp);
        float sc = __expf(m - mn);
        float a  = __expf(pp - mn);
        den = den * sc + a;
        #pragma unroll
        for (int v = 0; v < 16; v++) acc[v] = fmaf(acc[v], sc, a * t[v]);
        m = mn;
        t0 = n0; t1 = n1;
    }

    float inv = 1.f / (den + 1e-16f);
    float ov[16];
    #pragma unroll
    for (int v = 0; v < 16; v++) {
        float hv = acc[v] * inv;
        hv += __shfl_xor_sync(0xFFFFFFFFu, hv, 8);
        hv += __shfl_xor_sync(0xFFFFFFFFu, hv, 16);
        ov[v] = 0.25f * hv;
    }
    if (lane < 8) {
        uint4 s0 = *(const uint4*)(sl3 + (size_t)d * C3 + lane * 16);
        uint4 s1 = *(const uint4*)(sl3 + (size_t)d * C3 + lane * 16 + 8);
        const __half2* sh0 = (const __half2*)&s0;
        const __half2* sh1 = (const __half2*)&s1;
        float sv[16];
        #pragma unroll
        for (int j = 0; j < 4; j++) {
            float2 f0 = __half22float2(sh0[j]);
            float2 f1 = __half22float2(sh1[j]);
            sv[2*j] = f0.x; sv[2*j+1] = f0.y;
            sv[8+2*j] = f1.x; sv[8+2*j+1] = f1.y;
        }
        #pragma unroll
        for (int v = 0; v < 16; v++) {
            int c = lane * 16 + v;
            float x = ov[v] + bias3[c] + sv[v];
            ov[v] = x > 0.f ? x : (__expf(x) - 1.f);
        }
        float4* po = (float4*)(out + (size_t)d * C3 + lane * 16);
        #pragma unroll
        for (int q = 0; q < 4; q++)
            po[q] = make_float4(ov[q*4+0], ov[q*4+1], ov[q*4+2], ov[q*4+3]);
    }
}

// ---------------- host launch ----------------
static inline __half* symh(const void* s) {
    void* p = nullptr;
    cudaGetSymbolAddress(&p, s);
    return (__half*)p;
}
static inline float* symf(const void* s) {
    void* p = nullptr;
    cudaGetSymbolAddress(&p, s);
    return (float*)p;
}
static inline int* symi(const void* s) {
    void* p = nullptr;
    cudaGetSymbolAddress(&p, s);
    return (int*)p;
}

extern "C" void kernel_launch(void* const* d_in, const int* in_sizes, int n_in,
                              void* d_out, int out_size) {
    const float* x_sample = (const float*)d_in[0];
    const float* x_gene   = (const float*)d_in[1];
    const int*   sg_src   = (const int*)d_in[2];
    const int*   sg_dst   = (const int*)d_in[3];
    const int*   gs_src   = (const int*)d_in[4];
    const int*   gs_dst   = (const int*)d_in[5];
    const float* Wl1_sg = (const float*)d_in[6];
    const float* bl1_sg = (const float*)d_in[7];
    const float* Wr1_sg = (const float*)d_in[8];
    const float* br1_sg = (const float*)d_in[9];
    const float* att1_sg  = (const float*)d_in[10];
    const float* bias1_sg = (const float*)d_in[11];
    const float* Wl1_gs = (const float*)d_in[12];
    const float* bl1_gs = (const float*)d_in[13];
    const float* Wr1_gs = (const float*)d_in[14];
    const float* br1_gs = (const float*)d_in[15];
    const float* att1_gs  = (const float*)d_in[16];
    const float* bias1_gs = (const float*)d_in[17];
    const float* Wl3_gs = (const float*)d_in[18];
    const float* bl3_gs = (const float*)d_in[19];
    const float* Wr3_gs = (const float*)d_in[20];
    const float* br3_gs = (const float*)d_in[21];
    const float* att3_gs  = (const float*)d_in[22];
    const float* bias3_gs = (const float*)d_in[23];
    const float* sl1_W = (const float*)d_in[24];
    const float* sl1_b = (const float*)d_in[25];
    const float* sl3_W = (const float*)d_in[26];
    const float* sl3_b = (const float*)d_in[27];
    float* out = (float*)d_out;

    __half* xl_sg = symh(g_xl_sg);
    __half* xr_sg = symh(g_xr_sg);
    __half* xl_gs = symh(g_xl_gs);
    __half* xr_gs = symh(g_xr_gs);
    __half* sl1 = symh(g_sl1);
    __half* xl3 = symh(g_xl3);
    __half* xr3 = symh(g_xr3);
    __half* sl3 = symh(g_sl3);
    float* b5p = symf(g_b5p);
    __half* hxs = symh(g_hxs);
    __half* hxg = symh(g_hxg);
    __half* hWl1sg = symh(g_hWl1sg);
    __half* hWr1sg = symh(g_hWr1sg);
    __half* hWl1gs = symh(g_hWl1gs);
    __half* hWr1gs = symh(g_hWr1gs);
    __half* hw5 = symh(g_hw5);
    __half* hWl3 = symh(g_hWl3);
    __half* hWr3 = symh(g_hWr3);
    __half* hsl3W = symh(g_hsl3W);
    __half* x1h_gene = symh(g_x1h_gene);
    __half* x1h_sample = symh(g_x1h_sample);
    int* deg_sg = symi(g_deg_sg);
    int* deg_gs = symi(g_deg_gs);
    int* off_sg = symi(g_off_sg);
    int* cur_sg = symi(g_cur_sg);
    int* srcs_sg = symi(g_srcs_sg);
    int* off_gs = symi(g_off_gs);
    int* cur_gs = symi(g_cur_gs);
    int* srcs_gs = symi(g_srcs_gs);

    cudaFuncSetAttribute(gemm_batch, cudaFuncAttributeMaxDynamicSharedMemorySize, GEMM_SMEM);

    dim3 tb(256);
    int eb = (NE + 255) / 256;

    // ----- fork: CSR chain on side stream -----
    cudaStream_t sB;
    cudaStreamCreateWithFlags(&sB, cudaStreamNonBlocking);
    cudaEvent_t evFork, evJoin;
    cudaEventCreateWithFlags(&evFork, cudaEventDisableTiming);
    cudaEventCreateWithFlags(&evJoin, cudaEventDisableTiming);

    cudaEventRecord(evFork, 0);
    cudaStreamWaitEvent(sB, evFork, 0);

    cudaMemsetAsync(deg_sg, 0, NG * sizeof(int), sB);
    cudaMemsetAsync(deg_gs, 0, NS * sizeof(int), sB);
    count2_kernel<<<eb, tb, 0, sB>>>(sg_dst, gs_dst, deg_sg, deg_gs);
    scan2_kernel<<<2, 1024, 0, sB>>>(deg_sg, off_sg, cur_sg, deg_gs, off_gs, cur_gs);
    scatter2_kernel<<<eb, tb, 0, sB>>>(sg_src, sg_dst, cur_sg, srcs_sg,
                                       gs_src, gs_dst, cur_gs, srcs_gs);
    cudaEventRecord(evJoin, sB);

    // main stream: conversion + layer-1 GEMMs
    cvt_all<<<(NG * DIN / 4 + 255) / 256, tb>>>(
        x_sample, x_gene, Wl1_sg, Wr1_sg, Wl1_gs, Wr1_gs, sl1_W, sl1_b,
        Wl3_gs, Wr3_gs, sl3_W,
        hxs, hxg, hWl1sg, hWr1sg, hWl1gs, hWr1gs, hw5, b5p, hWl3, hWr3, hsl3W);

    const int MB_NS = NS / 128;            // 32
    const int MB_NG = (NG + 127) / 128;    // 157

    {
        GemmBatch P;
        int blk = 0;
        P.seg[0] = {hxs, hWl1sg, bl1_sg, xl_sg, HC1, NS, HC1, 2, blk}; blk += 2 * MB_NS;
        P.seg[1] = {hxg, hWr1sg, br1_sg, xr_sg, HC1, NG, HC1, 2, blk}; blk += 2 * MB_NG;
        P.seg[2] = {hxg, hWl1gs, bl1_gs, xl_gs, HC1, NG, HC1, 2, blk}; blk += 2 * MB_NG;
        P.seg[3] = {hxs, hWr1gs, br1_gs, xr_gs, HC1, NS, HC1, 2, blk}; blk += 2 * MB_NS;
        P.seg[4] = {hxs, hw5,    b5p,    sl1,   128, NS, C1,  1, blk}; blk += MB_NS;
        P.seg[5] = P.seg[4];
        P.nseg = 5;
        gemm_batch<<<blk, GEMM_THREADS, GEMM_SMEM>>>(P);
    }

    cudaStreamWaitEvent(0, evJoin, 0);

    gat1_dual<<<((NG + NS) * 32 + 255) / 256, tb>>>(
        off_sg, srcs_sg, xl_sg, xr_sg, att1_sg, bias1_sg, x1h_gene,
        off_gs, srcs_gs, xl_gs, xr_gs, att1_gs, bias1_gs, sl1, x1h_sample);

    {
        GemmBatch P;
        int blk = 0;
        P.seg[0] = {x1h_gene,   hWl3,  bl3_gs, xl3, HC3, NG, HC3, 4, blk}; blk += 4 * MB_NG;
        P.seg[1] = {x1h_sample, hWr3,  br3_gs, xr3, HC3, NS, HC3, 4, blk}; blk += 4 * MB_NS;
        P.seg[2] = {x1h_sample, hsl3W, sl3_b,  sl3, C3,  NS, C3,  1, blk}; blk += MB_NS;
        P.seg[3] = P.seg[2];
        P.seg[4] = P.seg[2];
        P.seg[5] = P.seg[2];
        P.nseg = 3;
        gemm_batch<<<blk, GEMM_THREADS, GEMM_SMEM>>>(P);
    }

    gat3_warp<<<(NS * 32 + 255) / 256, tb>>>(off_gs, srcs_gs, xl3, xr3, att3_gs, bias3_gs, sl3, out);
}